// round 1
// baseline (speedup 1.0000x reference)
#include <cuda_runtime.h>
#include <cstdint>

// ----------------------------------------------------------------------------
// Problem constants: B=4, T=S=1024, D=1024, H=16, hs=64, Dff=4096
// rows N = B*T = 4096
// ----------------------------------------------------------------------------

// Scratch buffers (device globals -- no allocation allowed)
__device__ float g_h0[4096 * 1024];     // rmsnorm(x)
__device__ float g_Qb[4096 * 2048];     // Q projection (2 streams)
__device__ float g_Kb[4096 * 2048];     // K projection (2 streams)
__device__ float g_Vb[4096 * 1024];     // V projection
__device__ float g_Ob[4096 * 1024];     // attention output (post head-rmsnorm)
__device__ float g_h1[4096 * 1024];     // after self-attn + residual
__device__ float g_h2[4096 * 1024];     // 2 * cross-attn output
__device__ float g_h3[4096 * 1024];     // rmsnorm(h2)
__device__ float g_G1[4096 * 4096];     // FFN gate
__device__ float g_G2[4096 * 4096];     // FFN up
__device__ float g_lam[32];             // lambda per head, [0..15] self, [16..31] cross

// ----------------------------------------------------------------------------
// lambda_h = exp(sum(lq1*lk1)) - exp(sum(lq2*lk2)) + 0.8
// ----------------------------------------------------------------------------
__global__ void lambda_kernel(const float* __restrict__ lq1, const float* __restrict__ lk1,
                              const float* __restrict__ lq2, const float* __restrict__ lk2,
                              float* __restrict__ out) {
    int h = threadIdx.x >> 5;
    int lane = threadIdx.x & 31;
    float s1 = lq1[h * 64 + lane] * lk1[h * 64 + lane] +
               lq1[h * 64 + 32 + lane] * lk1[h * 64 + 32 + lane];
    float s2 = lq2[h * 64 + lane] * lk2[h * 64 + lane] +
               lq2[h * 64 + 32 + lane] * lk2[h * 64 + 32 + lane];
    #pragma unroll
    for (int o = 16; o; o >>= 1) {
        s1 += __shfl_xor_sync(0xffffffffu, s1, o);
        s2 += __shfl_xor_sync(0xffffffffu, s2, o);
    }
    if (lane == 0) out[h] = __expf(s1) - __expf(s2) + 0.8f;
}

// ----------------------------------------------------------------------------
// RMSNorm over last dim (1024). One block (256 thr) per row.
// ----------------------------------------------------------------------------
__global__ void __launch_bounds__(256) rmsnorm_kernel(const float* __restrict__ x,
                                                      const float* __restrict__ g,
                                                      float* __restrict__ y) {
    int row = blockIdx.x;
    const float4* xr = (const float4*)(x + (size_t)row * 1024);
    float4 v = xr[threadIdx.x];
    float ss = v.x * v.x + v.y * v.y + v.z * v.z + v.w * v.w;
    #pragma unroll
    for (int o = 16; o; o >>= 1) ss += __shfl_xor_sync(0xffffffffu, ss, o);
    __shared__ float red[8];
    int w = threadIdx.x >> 5;
    if ((threadIdx.x & 31) == 0) red[w] = ss;
    __syncthreads();
    if (w == 0) {
        float t = (threadIdx.x < 8) ? red[threadIdx.x] : 0.f;
        #pragma unroll
        for (int o = 4; o; o >>= 1) t += __shfl_xor_sync(0xffffffffu, t, o);
        if (threadIdx.x == 0) red[0] = t;
    }
    __syncthreads();
    float r = rsqrtf(red[0] * (1.0f / 1024.0f) + 1e-6f);
    const float4* gr = (const float4*)g;
    float4 gv = gr[threadIdx.x];
    float4 o4 = make_float4(v.x * r * gv.x, v.y * r * gv.y, v.z * r * gv.z, v.w * r * gv.w);
    ((float4*)(y + (size_t)row * 1024))[threadIdx.x] = o4;
}

// ----------------------------------------------------------------------------
// fp32 SGEMM: C = alpha * A(MxK) @ B(KxN) [+ R]. Row-major. 128x128 tile,
// 256 threads, 8x8 microtile. M,N multiples of 128; K multiple of 8.
// ----------------------------------------------------------------------------
template <bool HAS_RES>
__global__ void __launch_bounds__(256) sgemm_kernel(const float* __restrict__ A,
                                                    const float* __restrict__ B,
                                                    float* __restrict__ C,
                                                    const float* __restrict__ R,
                                                    int M, int N, int K, float alpha) {
    __shared__ float As[8][128];
    __shared__ float Bs[8][128];
    const int tid = threadIdx.x;
    const int tx = tid & 15, ty = tid >> 4;
    const int row0 = blockIdx.y * 128, col0 = blockIdx.x * 128;
    const int arow = tid >> 1, akq = (tid & 1) * 4;
    const int brow = tid >> 5, bcol = (tid & 31) * 4;
    const float* Ap = A + (size_t)(row0 + arow) * K + akq;
    const float* Bp = B + (size_t)brow * N + col0 + bcol;

    float acc[8][8];
    #pragma unroll
    for (int i = 0; i < 8; i++)
        #pragma unroll
        for (int j = 0; j < 8; j++) acc[i][j] = 0.f;

    for (int k0 = 0; k0 < K; k0 += 8) {
        float4 av = *(const float4*)(Ap + k0);
        float4 bv = *(const float4*)(Bp + (size_t)k0 * N);
        As[akq + 0][arow] = av.x;
        As[akq + 1][arow] = av.y;
        As[akq + 2][arow] = av.z;
        As[akq + 3][arow] = av.w;
        *(float4*)&Bs[brow][bcol] = bv;
        __syncthreads();
        #pragma unroll
        for (int kk = 0; kk < 8; kk++) {
            float a[8], b[8];
            *(float4*)&a[0] = *(const float4*)&As[kk][ty * 4];
            *(float4*)&a[4] = *(const float4*)&As[kk][64 + ty * 4];
            *(float4*)&b[0] = *(const float4*)&Bs[kk][tx * 4];
            *(float4*)&b[4] = *(const float4*)&Bs[kk][64 + tx * 4];
            #pragma unroll
            for (int i = 0; i < 8; i++)
                #pragma unroll
                for (int j = 0; j < 8; j++) acc[i][j] = fmaf(a[i], b[j], acc[i][j]);
        }
        __syncthreads();
    }

    #pragma unroll
    for (int i = 0; i < 8; i++) {
        int r = row0 + ((i < 4) ? (ty * 4 + i) : (64 + ty * 4 + i - 4));
        #pragma unroll
        for (int jh = 0; jh < 2; jh++) {
            int c = col0 + jh * 64 + tx * 4;
            float4 v;
            v.x = acc[i][jh * 4 + 0] * alpha;
            v.y = acc[i][jh * 4 + 1] * alpha;
            v.z = acc[i][jh * 4 + 2] * alpha;
            v.w = acc[i][jh * 4 + 3] * alpha;
            if (HAS_RES) {
                float4 rv = *(const float4*)(R + (size_t)r * N + c);
                v.x += rv.x; v.y += rv.y; v.z += rv.z; v.w += rv.w;
            }
            *(float4*)(C + (size_t)r * N + c) = v;
        }
    }
}

// ----------------------------------------------------------------------------
// Differential flash attention.
//  Q,K layout: [B*T, 2048], stream1 col = h*128+d, stream2 col = h*128+64+d
//  V layout:   [B*S, 1024], col = h*64+d
//  O layout:   [B*T, 1024], col = h*64+d
// One block = one (b,h) x 64 query rows. 256 threads = 16x16 grid, 4x4 micro.
// Online softmax for both streams; epilogue: o = o1/l1 - lam*o2/l2,
// then rmsnorm over hs and * (1 - 0.8).
// ----------------------------------------------------------------------------
#define FA_PITCH 65
#define FA_SMEM_FLOATS (6 * 64 * FA_PITCH + 64 * 64)
#define FA_SMEM_BYTES (FA_SMEM_FLOATS * 4)

__global__ void __launch_bounds__(256) diff_flash_kernel(const float* __restrict__ Q,
                                                         const float* __restrict__ K,
                                                         const float* __restrict__ V,
                                                         float* __restrict__ O,
                                                         const float* __restrict__ lam,
                                                         int causal) {
    extern __shared__ float sm[];
    float* Q1t = sm;                       // [64][65], d-major
    float* Q2t = sm + 1 * 64 * FA_PITCH;
    float* K1t = sm + 2 * 64 * FA_PITCH;
    float* K2t = sm + 3 * 64 * FA_PITCH;
    float* Ps1 = sm + 4 * 64 * FA_PITCH;   // [s][r]
    float* Ps2 = sm + 5 * 64 * FA_PITCH;
    float* Vs  = sm + 6 * 64 * FA_PITCH;   // [s][d], 64x64

    const int tid = threadIdx.x;
    const int tx = tid & 15, ty = tid >> 4;
    const int bh = blockIdx.y;
    const int b = bh >> 4, h = bh & 15;
    const int t0 = blockIdx.x * 64;

    const size_t qbase = ((size_t)b * 1024 + t0) * 2048 + h * 128;
    const size_t kbase0 = ((size_t)b * 1024) * 2048 + h * 128;
    const size_t vbase0 = ((size_t)b * 1024) * 1024 + h * 64;

    // Load Q tiles, transposed (d-major) into smem
    #pragma unroll
    for (int it = 0; it < 4; it++) {
        int idx = tid + it * 256;
        int r = idx >> 4;
        int q = (idx & 15) * 4;
        float4 v1 = *(const float4*)(Q + qbase + (size_t)r * 2048 + q);
        float4 v2 = *(const float4*)(Q + qbase + (size_t)r * 2048 + 64 + q);
        Q1t[(q + 0) * FA_PITCH + r] = v1.x;
        Q1t[(q + 1) * FA_PITCH + r] = v1.y;
        Q1t[(q + 2) * FA_PITCH + r] = v1.z;
        Q1t[(q + 3) * FA_PITCH + r] = v1.w;
        Q2t[(q + 0) * FA_PITCH + r] = v2.x;
        Q2t[(q + 1) * FA_PITCH + r] = v2.y;
        Q2t[(q + 2) * FA_PITCH + r] = v2.z;
        Q2t[(q + 3) * FA_PITCH + r] = v2.w;
    }

    float m1[4], l1[4], m2[4], l2[4];
    float o1[4][4], o2[4][4];
    #pragma unroll
    for (int i = 0; i < 4; i++) {
        m1[i] = -1e30f; m2[i] = -1e30f; l1[i] = 0.f; l2[i] = 0.f;
        #pragma unroll
        for (int j = 0; j < 4; j++) { o1[i][j] = 0.f; o2[i][j] = 0.f; }
    }

    const int nS = causal ? (blockIdx.x + 1) : 16;
    const float scale = 0.125f;  // 1/sqrt(64)

    for (int si = 0; si < nS; si++) {
        const size_t kb = kbase0 + (size_t)si * 64 * 2048;
        const size_t vb = vbase0 + (size_t)si * 64 * 1024;
        __syncthreads();
        #pragma unroll
        for (int it = 0; it < 4; it++) {
            int idx = tid + it * 256;
            int r = idx >> 4;
            int q = (idx & 15) * 4;
            float4 kv1 = *(const float4*)(K + kb + (size_t)r * 2048 + q);
            float4 kv2 = *(const float4*)(K + kb + (size_t)r * 2048 + 64 + q);
            float4 vv  = *(const float4*)(V + vb + (size_t)r * 1024 + q);
            K1t[(q + 0) * FA_PITCH + r] = kv1.x;
            K1t[(q + 1) * FA_PITCH + r] = kv1.y;
            K1t[(q + 2) * FA_PITCH + r] = kv1.z;
            K1t[(q + 3) * FA_PITCH + r] = kv1.w;
            K2t[(q + 0) * FA_PITCH + r] = kv2.x;
            K2t[(q + 1) * FA_PITCH + r] = kv2.y;
            K2t[(q + 2) * FA_PITCH + r] = kv2.z;
            K2t[(q + 3) * FA_PITCH + r] = kv2.w;
            *(float4*)&Vs[r * 64 + q] = vv;
        }
        __syncthreads();

        // S = Q @ K^T (both streams)
        float s1r[4][4], s2r[4][4];
        #pragma unroll
        for (int i = 0; i < 4; i++)
            #pragma unroll
            for (int j = 0; j < 4; j++) { s1r[i][j] = 0.f; s2r[i][j] = 0.f; }

        #pragma unroll 4
        for (int d = 0; d < 64; d++) {
            float a1[4], a2[4], b1[4], b2[4];
            #pragma unroll
            for (int i = 0; i < 4; i++) {
                a1[i] = Q1t[d * FA_PITCH + ty + 16 * i];
                a2[i] = Q2t[d * FA_PITCH + ty + 16 * i];
            }
            #pragma unroll
            for (int j = 0; j < 4; j++) {
                b1[j] = K1t[d * FA_PITCH + tx + 16 * j];
                b2[j] = K2t[d * FA_PITCH + tx + 16 * j];
            }
            #pragma unroll
            for (int i = 0; i < 4; i++)
                #pragma unroll
                for (int j = 0; j < 4; j++) {
                    s1r[i][j] = fmaf(a1[i], b1[j], s1r[i][j]);
                    s2r[i][j] = fmaf(a2[i], b2[j], s2r[i][j]);
                }
        }

        const bool diag = (causal && si == (int)blockIdx.x);
        #pragma unroll
        for (int i = 0; i < 4; i++) {
            int rr = ty + 16 * i;
            #pragma unroll
            for (int j = 0; j < 4; j++) {
                float v1 = s1r[i][j] * scale;
                float v2 = s2r[i][j] * scale;
                if (diag && (tx + 16 * j) > rr) { v1 = -1e9f; v2 = -1e9f; }
                s1r[i][j] = v1;
                s2r[i][j] = v2;
            }
        }

        // online softmax update, both streams; write P transposed to smem
        #pragma unroll
        for (int i = 0; i < 4; i++) {
            // stream 1
            {
                float mx = fmaxf(fmaxf(s1r[i][0], s1r[i][1]), fmaxf(s1r[i][2], s1r[i][3]));
                mx = fmaxf(mx, __shfl_xor_sync(0xffffffffu, mx, 8));
                mx = fmaxf(mx, __shfl_xor_sync(0xffffffffu, mx, 4));
                mx = fmaxf(mx, __shfl_xor_sync(0xffffffffu, mx, 2));
                mx = fmaxf(mx, __shfl_xor_sync(0xffffffffu, mx, 1));
                float mn = fmaxf(m1[i], mx);
                float corr = __expf(m1[i] - mn);
                float rs = 0.f;
                #pragma unroll
                for (int j = 0; j < 4; j++) {
                    float p = __expf(s1r[i][j] - mn);
                    s1r[i][j] = p;
                    rs += p;
                }
                rs += __shfl_xor_sync(0xffffffffu, rs, 8);
                rs += __shfl_xor_sync(0xffffffffu, rs, 4);
                rs += __shfl_xor_sync(0xffffffffu, rs, 2);
                rs += __shfl_xor_sync(0xffffffffu, rs, 1);
                l1[i] = l1[i] * corr + rs;
                m1[i] = mn;
                #pragma unroll
                for (int j = 0; j < 4; j++) o1[i][j] *= corr;
                #pragma unroll
                for (int j = 0; j < 4; j++)
                    Ps1[(tx + 16 * j) * FA_PITCH + ty + 16 * i] = s1r[i][j];
            }
            // stream 2
            {
                float mx = fmaxf(fmaxf(s2r[i][0], s2r[i][1]), fmaxf(s2r[i][2], s2r[i][3]));
                mx = fmaxf(mx, __shfl_xor_sync(0xffffffffu, mx, 8));
                mx = fmaxf(mx, __shfl_xor_sync(0xffffffffu, mx, 4));
                mx = fmaxf(mx, __shfl_xor_sync(0xffffffffu, mx, 2));
                mx = fmaxf(mx, __shfl_xor_sync(0xffffffffu, mx, 1));
                float mn = fmaxf(m2[i], mx);
                float corr = __expf(m2[i] - mn);
                float rs = 0.f;
                #pragma unroll
                for (int j = 0; j < 4; j++) {
                    float p = __expf(s2r[i][j] - mn);
                    s2r[i][j] = p;
                    rs += p;
                }
                rs += __shfl_xor_sync(0xffffffffu, rs, 8);
                rs += __shfl_xor_sync(0xffffffffu, rs, 4);
                rs += __shfl_xor_sync(0xffffffffu, rs, 2);
                rs += __shfl_xor_sync(0xffffffffu, rs, 1);
                l2[i] = l2[i] * corr + rs;
                m2[i] = mn;
                #pragma unroll
                for (int j = 0; j < 4; j++) o2[i][j] *= corr;
                #pragma unroll
                for (int j = 0; j < 4; j++)
                    Ps2[(tx + 16 * j) * FA_PITCH + ty + 16 * i] = s2r[i][j];
            }
        }
        __syncthreads();

        // O += P @ V (both streams)
        #pragma unroll 4
        for (int s = 0; s < 64; s++) {
            float a1v[4], a2v[4], bv[4];
            #pragma unroll
            for (int i = 0; i < 4; i++) {
                a1v[i] = Ps1[s * FA_PITCH + ty + 16 * i];
                a2v[i] = Ps2[s * FA_PITCH + ty + 16 * i];
            }
            #pragma unroll
            for (int j = 0; j < 4; j++) bv[j] = Vs[s * 64 + tx + 16 * j];
            #pragma unroll
            for (int i = 0; i < 4; i++)
                #pragma unroll
                for (int j = 0; j < 4; j++) {
                    o1[i][j] = fmaf(a1v[i], bv[j], o1[i][j]);
                    o2[i][j] = fmaf(a2v[i], bv[j], o2[i][j]);
                }
        }
    }

    // epilogue: combine, per-row rmsnorm over hs, scale by (1 - 0.8)
    const float lv = lam[h];
    const size_t obase = ((size_t)b * 1024 + t0) * 1024 + h * 64;
    #pragma unroll
    for (int i = 0; i < 4; i++) {
        float inv1 = 1.f / l1[i];
        float inv2 = 1.f / l2[i];
        float of[4];
        float ss = 0.f;
        #pragma unroll
        for (int j = 0; j < 4; j++) {
            of[j] = o1[i][j] * inv1 - lv * (o2[i][j] * inv2);
            ss += of[j] * of[j];
        }
        ss += __shfl_xor_sync(0xffffffffu, ss, 8);
        ss += __shfl_xor_sync(0xffffffffu, ss, 4);
        ss += __shfl_xor_sync(0xffffffffu, ss, 2);
        ss += __shfl_xor_sync(0xffffffffu, ss, 1);
        float rn = rsqrtf(ss * (1.0f / 64.0f) + 1e-6f) * 0.2f;
        #pragma unroll
        for (int j = 0; j < 4; j++)
            O[obase + (size_t)(ty + 16 * i) * 1024 + tx + 16 * j] = of[j] * rn;
    }
}

// ----------------------------------------------------------------------------
// y = silu(g1) * g2 (elementwise, float4)
// ----------------------------------------------------------------------------
__global__ void silu_mul_kernel(const float* __restrict__ g1, const float* __restrict__ g2,
                                float* __restrict__ y, int n4) {
    int i = blockIdx.x * blockDim.x + threadIdx.x;
    int stride = gridDim.x * blockDim.x;
    for (; i < n4; i += stride) {
        float4 a = ((const float4*)g1)[i];
        float4 b = ((const float4*)g2)[i];
        float4 r;
        r.x = a.x / (1.f + __expf(-a.x)) * b.x;
        r.y = a.y / (1.f + __expf(-a.y)) * b.y;
        r.z = a.z / (1.f + __expf(-a.z)) * b.z;
        r.w = a.w / (1.f + __expf(-a.w)) * b.w;
        ((float4*)y)[i] = r;
    }
}

// ----------------------------------------------------------------------------
// kernel_launch
// ----------------------------------------------------------------------------
extern "C" void kernel_launch(void* const* d_in, const int* in_sizes, int n_in,
                              void* d_out, int out_size) {
    const float* x     = (const float*)d_in[0];
    const float* enc   = (const float*)d_in[1];
    const float* Wq_s  = (const float*)d_in[2];
    const float* Wk_s  = (const float*)d_in[3];
    const float* Wv_s  = (const float*)d_in[4];
    const float* Wo_s  = (const float*)d_in[5];
    const float* lq1_s = (const float*)d_in[6];
    const float* lk1_s = (const float*)d_in[7];
    const float* lq2_s = (const float*)d_in[8];
    const float* lk2_s = (const float*)d_in[9];
    const float* Wq_c  = (const float*)d_in[10];
    const float* Wk_c  = (const float*)d_in[11];
    const float* Wv_c  = (const float*)d_in[12];
    const float* Wo_c  = (const float*)d_in[13];
    const float* lq1_c = (const float*)d_in[14];
    const float* lk1_c = (const float*)d_in[15];
    const float* lq2_c = (const float*)d_in[16];
    const float* lk2_c = (const float*)d_in[17];
    const float* grms  = (const float*)d_in[18];
    const float* W1    = (const float*)d_in[19];
    const float* W2    = (const float*)d_in[20];
    const float* W3    = (const float*)d_in[21];
    float* out = (float*)d_out;

    float *h0, *Qb, *Kb, *Vb, *Ob, *h1, *h2, *h3, *G1, *G2, *lam;
    cudaGetSymbolAddress((void**)&h0, g_h0);
    cudaGetSymbolAddress((void**)&Qb, g_Qb);
    cudaGetSymbolAddress((void**)&Kb, g_Kb);
    cudaGetSymbolAddress((void**)&Vb, g_Vb);
    cudaGetSymbolAddress((void**)&Ob, g_Ob);
    cudaGetSymbolAddress((void**)&h1, g_h1);
    cudaGetSymbolAddress((void**)&h2, g_h2);
    cudaGetSymbolAddress((void**)&h3, g_h3);
    cudaGetSymbolAddress((void**)&G1, g_G1);
    cudaGetSymbolAddress((void**)&G2, g_G2);
    cudaGetSymbolAddress((void**)&lam, g_lam);

    cudaFuncSetAttribute(diff_flash_kernel, cudaFuncAttributeMaxDynamicSharedMemorySize,
                         FA_SMEM_BYTES);

    // lambdas for both attention layers
    lambda_kernel<<<1, 512>>>(lq1_s, lk1_s, lq2_s, lk2_s, lam);
    lambda_kernel<<<1, 512>>>(lq1_c, lk1_c, lq2_c, lk2_c, lam + 16);

    // h0 = rmsnorm(x)
    rmsnorm_kernel<<<4096, 256>>>(x, grms, h0);

    // ---- self attention (causal) ----
    sgemm_kernel<false><<<dim3(16, 32), 256>>>(h0, Wq_s, Qb, nullptr, 4096, 2048, 1024, 1.f);
    sgemm_kernel<false><<<dim3(16, 32), 256>>>(h0, Wk_s, Kb, nullptr, 4096, 2048, 1024, 1.f);
    sgemm_kernel<false><<<dim3(8, 32), 256>>>(h0, Wv_s, Vb, nullptr, 4096, 1024, 1024, 1.f);
    diff_flash_kernel<<<dim3(16, 64), 256, FA_SMEM_BYTES>>>(Qb, Kb, Vb, Ob, lam, 1);
    // h1 = O @ Wo_s + h0
    sgemm_kernel<true><<<dim3(8, 32), 256>>>(Ob, Wo_s, h1, h0, 4096, 1024, 1024, 1.f);

    // ---- cross attention (non-causal, kv = encoder_output) ----
    sgemm_kernel<false><<<dim3(16, 32), 256>>>(h1, Wq_c, Qb, nullptr, 4096, 2048, 1024, 1.f);
    sgemm_kernel<false><<<dim3(16, 32), 256>>>(enc, Wk_c, Kb, nullptr, 4096, 2048, 1024, 1.f);
    sgemm_kernel<false><<<dim3(8, 32), 256>>>(enc, Wv_c, Vb, nullptr, 4096, 1024, 1024, 1.f);
    diff_flash_kernel<<<dim3(16, 64), 256, FA_SMEM_BYTES>>>(Qb, Kb, Vb, Ob, lam + 16, 0);
    // h2 = 2 * (O @ Wo_c)   (reference: h = attn_out; h = h + h)
    sgemm_kernel<false><<<dim3(8, 32), 256>>>(Ob, Wo_c, h2, nullptr, 4096, 1024, 1024, 2.f);

    // ---- FFN: out = swiglu(rmsnorm(h2)) + h2 ----
    rmsnorm_kernel<<<4096, 256>>>(h2, grms, h3);
    sgemm_kernel<false><<<dim3(32, 32), 256>>>(h3, W1, G1, nullptr, 4096, 4096, 1024, 1.f);
    sgemm_kernel<false><<<dim3(32, 32), 256>>>(h3, W2, G2, nullptr, 4096, 4096, 1024, 1.f);
    silu_mul_kernel<<<4096, 256>>>(G1, G2, G1, 4096 * 4096 / 4);
    sgemm_kernel<true><<<dim3(8, 32), 256>>>(G1, W3, out, h2, 4096, 1024, 4096, 1.f);
}

// round 2
// speedup vs baseline: 1.5560x; 1.5560x over previous
#include <cuda_runtime.h>
#include <cstdint>

// ----------------------------------------------------------------------------
// Problem constants: B=4, T=S=1024, D=1024, H=16, hs=64, Dff=4096
// ----------------------------------------------------------------------------

__device__ float g_h0[4096 * 1024];
__device__ float g_Qb[4096 * 2048];
__device__ float g_Kb[4096 * 2048];
__device__ float g_Vb[4096 * 1024];
__device__ float g_Ob[4096 * 1024];
__device__ float g_h1[4096 * 1024];
__device__ float g_h2[4096 * 1024];
__device__ float g_h3[4096 * 1024];
__device__ float g_G1[4096 * 4096];
__device__ float g_G2[4096 * 4096];
__device__ float g_lam[32];

__device__ __forceinline__ uint32_t f2tf(float x) {
    uint32_t r;
    asm("cvt.rna.tf32.f32 %0, %1;" : "=r"(r) : "f"(x));
    return r;
}

// ----------------------------------------------------------------------------
// lambda_h = exp(sum(lq1*lk1)) - exp(sum(lq2*lk2)) + 0.8
// ----------------------------------------------------------------------------
__global__ void lambda_kernel(const float* __restrict__ lq1, const float* __restrict__ lk1,
                              const float* __restrict__ lq2, const float* __restrict__ lk2,
                              float* __restrict__ out) {
    int h = threadIdx.x >> 5;
    int lane = threadIdx.x & 31;
    float s1 = lq1[h * 64 + lane] * lk1[h * 64 + lane] +
               lq1[h * 64 + 32 + lane] * lk1[h * 64 + 32 + lane];
    float s2 = lq2[h * 64 + lane] * lk2[h * 64 + lane] +
               lq2[h * 64 + 32 + lane] * lk2[h * 64 + 32 + lane];
    #pragma unroll
    for (int o = 16; o; o >>= 1) {
        s1 += __shfl_xor_sync(0xffffffffu, s1, o);
        s2 += __shfl_xor_sync(0xffffffffu, s2, o);
    }
    if (lane == 0) out[h] = __expf(s1) - __expf(s2) + 0.8f;
}

// ----------------------------------------------------------------------------
// RMSNorm over last dim (1024). One block (256 thr) per row.
// ----------------------------------------------------------------------------
__global__ void __launch_bounds__(256) rmsnorm_kernel(const float* __restrict__ x,
                                                      const float* __restrict__ g,
                                                      float* __restrict__ y) {
    int row = blockIdx.x;
    const float4* xr = (const float4*)(x + (size_t)row * 1024);
    float4 v = xr[threadIdx.x];
    float ss = v.x * v.x + v.y * v.y + v.z * v.z + v.w * v.w;
    #pragma unroll
    for (int o = 16; o; o >>= 1) ss += __shfl_xor_sync(0xffffffffu, ss, o);
    __shared__ float red[8];
    int w = threadIdx.x >> 5;
    if ((threadIdx.x & 31) == 0) red[w] = ss;
    __syncthreads();
    if (w == 0) {
        float t = (threadIdx.x < 8) ? red[threadIdx.x] : 0.f;
        #pragma unroll
        for (int o = 4; o; o >>= 1) t += __shfl_xor_sync(0xffffffffu, t, o);
        if (threadIdx.x == 0) red[0] = t;
    }
    __syncthreads();
    float r = rsqrtf(red[0] * (1.0f / 1024.0f) + 1e-6f);
    const float4* gr = (const float4*)g;
    float4 gv = gr[threadIdx.x];
    float4 o4 = make_float4(v.x * r * gv.x, v.y * r * gv.y, v.z * r * gv.z, v.w * r * gv.w);
    ((float4*)(y + (size_t)row * 1024))[threadIdx.x] = o4;
}

// ----------------------------------------------------------------------------
// TF32 tensor-core GEMM: C = alpha * A(MxK)@B(KxN) [+ R]. Row-major.
// 128x128x32 tiles, 256 thr (8 warps 2x4, warp tile 64x32), mma.m16n8k8.tf32,
// double-buffered smem with XOR swizzle (conflict-free STS, ~CF frag LDS).
// ----------------------------------------------------------------------------
#define GA_STRIDE (32 * 129)
#define GB_STRIDE (32 * 132)
#define GEMM_SMEM ((2 * GA_STRIDE + 2 * GB_STRIDE) * 4)

template <bool HAS_RES>
__global__ void __launch_bounds__(256) tf32_gemm(const float* __restrict__ A,
                                                 const float* __restrict__ B,
                                                 float* __restrict__ C,
                                                 const float* __restrict__ R,
                                                 int M, int N, int K, float alpha) {
    extern __shared__ uint32_t sm_u[];
    uint32_t* As = sm_u;                 // [2][32][129] (k-major, col = row ^ ((k&3)<<3))
    uint32_t* Bs = sm_u + 2 * GA_STRIDE; // [2][32][132] (k-major, col = col ^ ((k&3)<<3))

    const int tid = threadIdx.x;
    const int lane = tid & 31;
    const int warp = tid >> 5;
    const int wm = warp >> 2, wn = warp & 3;
    const int g = lane >> 2, tg = lane & 3;
    const int row0 = blockIdx.y * 128, col0 = blockIdx.x * 128;

    float acc[4][4][4];
    #pragma unroll
    for (int mi = 0; mi < 4; mi++)
        #pragma unroll
        for (int ni = 0; ni < 4; ni++)
            #pragma unroll
            for (int q = 0; q < 4; q++) acc[mi][ni][q] = 0.f;

    float4 ra[4], rb[4];

    auto load_g = [&](int kt) {
        #pragma unroll
        for (int i = 0; i < 4; i++) {
            int idx = tid + i * 256;
            ra[i] = *(const float4*)(A + (size_t)(row0 + (idx >> 3)) * K + kt * 32 + (idx & 7) * 4);
            rb[i] = *(const float4*)(B + (size_t)(kt * 32 + (idx >> 5)) * N + col0 + (idx & 31) * 4);
        }
    };

    auto store_s = [&](int buf) {
        uint32_t* Ab = As + buf * GA_STRIDE;
        uint32_t* Bb = Bs + buf * GB_STRIDE;
        #pragma unroll
        for (int i = 0; i < 4; i++) {
            int idx = tid + i * 256;
            int arow = idx >> 3, akk = (idx & 7) * 4;
            Ab[(akk + 0) * 129 + (arow ^ 0)]  = f2tf(ra[i].x);
            Ab[(akk + 1) * 129 + (arow ^ 8)]  = f2tf(ra[i].y);
            Ab[(akk + 2) * 129 + (arow ^ 16)] = f2tf(ra[i].z);
            Ab[(akk + 3) * 129 + (arow ^ 24)] = f2tf(ra[i].w);
            int brow = idx >> 5, bcol = (idx & 31) * 4;
            uint4 t;
            t.x = f2tf(rb[i].x); t.y = f2tf(rb[i].y);
            t.z = f2tf(rb[i].z); t.w = f2tf(rb[i].w);
            *(uint4*)&Bb[brow * 132 + (bcol ^ ((brow & 3) << 3))] = t;
        }
    };

    auto compute = [&](int buf) {
        const uint32_t* Ab = As + buf * GA_STRIDE;
        const uint32_t* Bb = Bs + buf * GB_STRIDE;
        const int xa = tg << 3;
        #pragma unroll
        for (int ks = 0; ks < 4; ks++) {
            const int kb = ks * 8 + tg;
            uint32_t a[4][4], b[4][2];
            #pragma unroll
            for (int mi = 0; mi < 4; mi++) {
                int r = wm * 64 + mi * 16 + g;
                a[mi][0] = Ab[kb * 129 + (r ^ xa)];
                a[mi][1] = Ab[kb * 129 + ((r + 8) ^ xa)];
                a[mi][2] = Ab[(kb + 4) * 129 + (r ^ xa)];
                a[mi][3] = Ab[(kb + 4) * 129 + ((r + 8) ^ xa)];
            }
            #pragma unroll
            for (int ni = 0; ni < 4; ni++) {
                int c = wn * 32 + ni * 8 + g;
                b[ni][0] = Bb[kb * 132 + (c ^ xa)];
                b[ni][1] = Bb[(kb + 4) * 132 + (c ^ xa)];
            }
            #pragma unroll
            for (int mi = 0; mi < 4; mi++)
                #pragma unroll
                for (int ni = 0; ni < 4; ni++) {
                    asm volatile(
                        "mma.sync.aligned.m16n8k8.row.col.f32.tf32.tf32.f32 "
                        "{%0,%1,%2,%3}, {%4,%5,%6,%7}, {%8,%9}, {%0,%1,%2,%3};\n"
                        : "+f"(acc[mi][ni][0]), "+f"(acc[mi][ni][1]),
                          "+f"(acc[mi][ni][2]), "+f"(acc[mi][ni][3])
                        : "r"(a[mi][0]), "r"(a[mi][1]), "r"(a[mi][2]), "r"(a[mi][3]),
                          "r"(b[ni][0]), "r"(b[ni][1]));
                }
        }
    };

    const int KT = K >> 5;
    load_g(0);
    store_s(0);
    for (int kt = 0; kt < KT; kt++) {
        __syncthreads();
        if (kt + 1 < KT) load_g(kt + 1);
        compute(kt & 1);
        if (kt + 1 < KT) store_s((kt + 1) & 1);
    }

    // epilogue
    #pragma unroll
    for (int mi = 0; mi < 4; mi++) {
        #pragma unroll
        for (int half = 0; half < 2; half++) {
            int r = row0 + wm * 64 + mi * 16 + g + half * 8;
            #pragma unroll
            for (int ni = 0; ni < 4; ni++) {
                int c = col0 + wn * 32 + ni * 8 + tg * 2;
                float v0 = acc[mi][ni][half * 2 + 0] * alpha;
                float v1 = acc[mi][ni][half * 2 + 1] * alpha;
                if (HAS_RES) {
                    float2 rv = *(const float2*)(R + (size_t)r * N + c);
                    v0 += rv.x; v1 += rv.y;
                }
                float2 o;
                o.x = v0; o.y = v1;
                *(float2*)(C + (size_t)r * N + c) = o;
            }
        }
    }
}

// ----------------------------------------------------------------------------
// Differential flash attention (fp32). Unchanged from R1.
// ----------------------------------------------------------------------------
#define FA_PITCH 65
#define FA_SMEM_FLOATS (6 * 64 * FA_PITCH + 64 * 64)
#define FA_SMEM_BYTES (FA_SMEM_FLOATS * 4)

__global__ void __launch_bounds__(256) diff_flash_kernel(const float* __restrict__ Q,
                                                         const float* __restrict__ K,
                                                         const float* __restrict__ V,
                                                         float* __restrict__ O,
                                                         const float* __restrict__ lam,
                                                         int causal) {
    extern __shared__ float sm[];
    float* Q1t = sm;
    float* Q2t = sm + 1 * 64 * FA_PITCH;
    float* K1t = sm + 2 * 64 * FA_PITCH;
    float* K2t = sm + 3 * 64 * FA_PITCH;
    float* Ps1 = sm + 4 * 64 * FA_PITCH;
    float* Ps2 = sm + 5 * 64 * FA_PITCH;
    float* Vs  = sm + 6 * 64 * FA_PITCH;

    const int tid = threadIdx.x;
    const int tx = tid & 15, ty = tid >> 4;
    const int bh = blockIdx.y;
    const int b = bh >> 4, h = bh & 15;
    const int t0 = blockIdx.x * 64;

    const size_t qbase = ((size_t)b * 1024 + t0) * 2048 + h * 128;
    const size_t kbase0 = ((size_t)b * 1024) * 2048 + h * 128;
    const size_t vbase0 = ((size_t)b * 1024) * 1024 + h * 64;

    #pragma unroll
    for (int it = 0; it < 4; it++) {
        int idx = tid + it * 256;
        int r = idx >> 4;
        int q = (idx & 15) * 4;
        float4 v1 = *(const float4*)(Q + qbase + (size_t)r * 2048 + q);
        float4 v2 = *(const float4*)(Q + qbase + (size_t)r * 2048 + 64 + q);
        Q1t[(q + 0) * FA_PITCH + r] = v1.x;
        Q1t[(q + 1) * FA_PITCH + r] = v1.y;
        Q1t[(q + 2) * FA_PITCH + r] = v1.z;
        Q1t[(q + 3) * FA_PITCH + r] = v1.w;
        Q2t[(q + 0) * FA_PITCH + r] = v2.x;
        Q2t[(q + 1) * FA_PITCH + r] = v2.y;
        Q2t[(q + 2) * FA_PITCH + r] = v2.z;
        Q2t[(q + 3) * FA_PITCH + r] = v2.w;
    }

    float m1[4], l1[4], m2[4], l2[4];
    float o1[4][4], o2[4][4];
    #pragma unroll
    for (int i = 0; i < 4; i++) {
        m1[i] = -1e30f; m2[i] = -1e30f; l1[i] = 0.f; l2[i] = 0.f;
        #pragma unroll
        for (int j = 0; j < 4; j++) { o1[i][j] = 0.f; o2[i][j] = 0.f; }
    }

    const int nS = causal ? (blockIdx.x + 1) : 16;
    const float scale = 0.125f;

    for (int si = 0; si < nS; si++) {
        const size_t kb = kbase0 + (size_t)si * 64 * 2048;
        const size_t vb = vbase0 + (size_t)si * 64 * 1024;
        __syncthreads();
        #pragma unroll
        for (int it = 0; it < 4; it++) {
            int idx = tid + it * 256;
            int r = idx >> 4;
            int q = (idx & 15) * 4;
            float4 kv1 = *(const float4*)(K + kb + (size_t)r * 2048 + q);
            float4 kv2 = *(const float4*)(K + kb + (size_t)r * 2048 + 64 + q);
            float4 vv  = *(const float4*)(V + vb + (size_t)r * 1024 + q);
            K1t[(q + 0) * FA_PITCH + r] = kv1.x;
            K1t[(q + 1) * FA_PITCH + r] = kv1.y;
            K1t[(q + 2) * FA_PITCH + r] = kv1.z;
            K1t[(q + 3) * FA_PITCH + r] = kv1.w;
            K2t[(q + 0) * FA_PITCH + r] = kv2.x;
            K2t[(q + 1) * FA_PITCH + r] = kv2.y;
            K2t[(q + 2) * FA_PITCH + r] = kv2.z;
            K2t[(q + 3) * FA_PITCH + r] = kv2.w;
            *(float4*)&Vs[r * 64 + q] = vv;
        }
        __syncthreads();

        float s1r[4][4], s2r[4][4];
        #pragma unroll
        for (int i = 0; i < 4; i++)
            #pragma unroll
            for (int j = 0; j < 4; j++) { s1r[i][j] = 0.f; s2r[i][j] = 0.f; }

        #pragma unroll 4
        for (int d = 0; d < 64; d++) {
            float a1[4], a2[4], b1[4], b2[4];
            #pragma unroll
            for (int i = 0; i < 4; i++) {
                a1[i] = Q1t[d * FA_PITCH + ty + 16 * i];
                a2[i] = Q2t[d * FA_PITCH + ty + 16 * i];
            }
            #pragma unroll
            for (int j = 0; j < 4; j++) {
                b1[j] = K1t[d * FA_PITCH + tx + 16 * j];
                b2[j] = K2t[d * FA_PITCH + tx + 16 * j];
            }
            #pragma unroll
            for (int i = 0; i < 4; i++)
                #pragma unroll
                for (int j = 0; j < 4; j++) {
                    s1r[i][j] = fmaf(a1[i], b1[j], s1r[i][j]);
                    s2r[i][j] = fmaf(a2[i], b2[j], s2r[i][j]);
                }
        }

        const bool diag = (causal && si == (int)blockIdx.x);
        #pragma unroll
        for (int i = 0; i < 4; i++) {
            int rr = ty + 16 * i;
            #pragma unroll
            for (int j = 0; j < 4; j++) {
                float v1 = s1r[i][j] * scale;
                float v2 = s2r[i][j] * scale;
                if (diag && (tx + 16 * j) > rr) { v1 = -1e9f; v2 = -1e9f; }
                s1r[i][j] = v1;
                s2r[i][j] = v2;
            }
        }

        #pragma unroll
        for (int i = 0; i < 4; i++) {
            {
                float mx = fmaxf(fmaxf(s1r[i][0], s1r[i][1]), fmaxf(s1r[i][2], s1r[i][3]));
                mx = fmaxf(mx, __shfl_xor_sync(0xffffffffu, mx, 8));
                mx = fmaxf(mx, __shfl_xor_sync(0xffffffffu, mx, 4));
                mx = fmaxf(mx, __shfl_xor_sync(0xffffffffu, mx, 2));
                mx = fmaxf(mx, __shfl_xor_sync(0xffffffffu, mx, 1));
                float mn = fmaxf(m1[i], mx);
                float corr = __expf(m1[i] - mn);
                float rs = 0.f;
                #pragma unroll
                for (int j = 0; j < 4; j++) {
                    float p = __expf(s1r[i][j] - mn);
                    s1r[i][j] = p;
                    rs += p;
                }
                rs += __shfl_xor_sync(0xffffffffu, rs, 8);
                rs += __shfl_xor_sync(0xffffffffu, rs, 4);
                rs += __shfl_xor_sync(0xffffffffu, rs, 2);
                rs += __shfl_xor_sync(0xffffffffu, rs, 1);
                l1[i] = l1[i] * corr + rs;
                m1[i] = mn;
                #pragma unroll
                for (int j = 0; j < 4; j++) o1[i][j] *= corr;
                #pragma unroll
                for (int j = 0; j < 4; j++)
                    Ps1[(tx + 16 * j) * FA_PITCH + ty + 16 * i] = s1r[i][j];
            }
            {
                float mx = fmaxf(fmaxf(s2r[i][0], s2r[i][1]), fmaxf(s2r[i][2], s2r[i][3]));
                mx = fmaxf(mx, __shfl_xor_sync(0xffffffffu, mx, 8));
                mx = fmaxf(mx, __shfl_xor_sync(0xffffffffu, mx, 4));
                mx = fmaxf(mx, __shfl_xor_sync(0xffffffffu, mx, 2));
                mx = fmaxf(mx, __shfl_xor_sync(0xffffffffu, mx, 1));
                float mn = fmaxf(m2[i], mx);
                float corr = __expf(m2[i] - mn);
                float rs = 0.f;
                #pragma unroll
                for (int j = 0; j < 4; j++) {
                    float p = __expf(s2r[i][j] - mn);
                    s2r[i][j] = p;
                    rs += p;
                }
                rs += __shfl_xor_sync(0xffffffffu, rs, 8);
                rs += __shfl_xor_sync(0xffffffffu, rs, 4);
                rs += __shfl_xor_sync(0xffffffffu, rs, 2);
                rs += __shfl_xor_sync(0xffffffffu, rs, 1);
                l2[i] = l2[i] * corr + rs;
                m2[i] = mn;
                #pragma unroll
                for (int j = 0; j < 4; j++) o2[i][j] *= corr;
                #pragma unroll
                for (int j = 0; j < 4; j++)
                    Ps2[(tx + 16 * j) * FA_PITCH + ty + 16 * i] = s2r[i][j];
            }
        }
        __syncthreads();

        #pragma unroll 4
        for (int s = 0; s < 64; s++) {
            float a1v[4], a2v[4], bv[4];
            #pragma unroll
            for (int i = 0; i < 4; i++) {
                a1v[i] = Ps1[s * FA_PITCH + ty + 16 * i];
                a2v[i] = Ps2[s * FA_PITCH + ty + 16 * i];
            }
            #pragma unroll
            for (int j = 0; j < 4; j++) bv[j] = Vs[s * 64 + tx + 16 * j];
            #pragma unroll
            for (int i = 0; i < 4; i++)
                #pragma unroll
                for (int j = 0; j < 4; j++) {
                    o1[i][j] = fmaf(a1v[i], bv[j], o1[i][j]);
                    o2[i][j] = fmaf(a2v[i], bv[j], o2[i][j]);
                }
        }
    }

    const float lv = lam[h];
    const size_t obase = ((size_t)b * 1024 + t0) * 1024 + h * 64;
    #pragma unroll
    for (int i = 0; i < 4; i++) {
        float inv1 = 1.f / l1[i];
        float inv2 = 1.f / l2[i];
        float of[4];
        float ss = 0.f;
        #pragma unroll
        for (int j = 0; j < 4; j++) {
            of[j] = o1[i][j] * inv1 - lv * (o2[i][j] * inv2);
            ss += of[j] * of[j];
        }
        ss += __shfl_xor_sync(0xffffffffu, ss, 8);
        ss += __shfl_xor_sync(0xffffffffu, ss, 4);
        ss += __shfl_xor_sync(0xffffffffu, ss, 2);
        ss += __shfl_xor_sync(0xffffffffu, ss, 1);
        float rn = rsqrtf(ss * (1.0f / 64.0f) + 1e-6f) * 0.2f;
        #pragma unroll
        for (int j = 0; j < 4; j++)
            O[obase + (size_t)(ty + 16 * i) * 1024 + tx + 16 * j] = of[j] * rn;
    }
}

// ----------------------------------------------------------------------------
// y = silu(g1) * g2 (elementwise, float4)
// ----------------------------------------------------------------------------
__global__ void silu_mul_kernel(const float* __restrict__ g1, const float* __restrict__ g2,
                                float* __restrict__ y, int n4) {
    int i = blockIdx.x * blockDim.x + threadIdx.x;
    int stride = gridDim.x * blockDim.x;
    for (; i < n4; i += stride) {
        float4 a = ((const float4*)g1)[i];
        float4 b = ((const float4*)g2)[i];
        float4 r;
        r.x = a.x / (1.f + __expf(-a.x)) * b.x;
        r.y = a.y / (1.f + __expf(-a.y)) * b.y;
        r.z = a.z / (1.f + __expf(-a.z)) * b.z;
        r.w = a.w / (1.f + __expf(-a.w)) * b.w;
        ((float4*)y)[i] = r;
    }
}

// ----------------------------------------------------------------------------
// kernel_launch
// ----------------------------------------------------------------------------
extern "C" void kernel_launch(void* const* d_in, const int* in_sizes, int n_in,
                              void* d_out, int out_size) {
    const float* x     = (const float*)d_in[0];
    const float* enc   = (const float*)d_in[1];
    const float* Wq_s  = (const float*)d_in[2];
    const float* Wk_s  = (const float*)d_in[3];
    const float* Wv_s  = (const float*)d_in[4];
    const float* Wo_s  = (const float*)d_in[5];
    const float* lq1_s = (const float*)d_in[6];
    const float* lk1_s = (const float*)d_in[7];
    const float* lq2_s = (const float*)d_in[8];
    const float* lk2_s = (const float*)d_in[9];
    const float* Wq_c  = (const float*)d_in[10];
    const float* Wk_c  = (const float*)d_in[11];
    const float* Wv_c  = (const float*)d_in[12];
    const float* Wo_c  = (const float*)d_in[13];
    const float* lq1_c = (const float*)d_in[14];
    const float* lk1_c = (const float*)d_in[15];
    const float* lq2_c = (const float*)d_in[16];
    const float* lk2_c = (const float*)d_in[17];
    const float* grms  = (const float*)d_in[18];
    const float* W1    = (const float*)d_in[19];
    const float* W2    = (const float*)d_in[20];
    const float* W3    = (const float*)d_in[21];
    float* out = (float*)d_out;

    float *h0, *Qb, *Kb, *Vb, *Ob, *h1, *h2, *h3, *G1, *G2, *lam;
    cudaGetSymbolAddress((void**)&h0, g_h0);
    cudaGetSymbolAddress((void**)&Qb, g_Qb);
    cudaGetSymbolAddress((void**)&Kb, g_Kb);
    cudaGetSymbolAddress((void**)&Vb, g_Vb);
    cudaGetSymbolAddress((void**)&Ob, g_Ob);
    cudaGetSymbolAddress((void**)&h1, g_h1);
    cudaGetSymbolAddress((void**)&h2, g_h2);
    cudaGetSymbolAddress((void**)&h3, g_h3);
    cudaGetSymbolAddress((void**)&G1, g_G1);
    cudaGetSymbolAddress((void**)&G2, g_G2);
    cudaGetSymbolAddress((void**)&lam, g_lam);

    cudaFuncSetAttribute(diff_flash_kernel, cudaFuncAttributeMaxDynamicSharedMemorySize,
                         FA_SMEM_BYTES);
    cudaFuncSetAttribute(tf32_gemm<false>, cudaFuncAttributeMaxDynamicSharedMemorySize,
                         GEMM_SMEM);
    cudaFuncSetAttribute(tf32_gemm<true>, cudaFuncAttributeMaxDynamicSharedMemorySize,
                         GEMM_SMEM);

    lambda_kernel<<<1, 512>>>(lq1_s, lk1_s, lq2_s, lk2_s, lam);
    lambda_kernel<<<1, 512>>>(lq1_c, lk1_c, lq2_c, lk2_c, lam + 16);

    rmsnorm_kernel<<<4096, 256>>>(x, grms, h0);

    // ---- self attention (causal) ----
    tf32_gemm<false><<<dim3(16, 32), 256, GEMM_SMEM>>>(h0, Wq_s, Qb, nullptr, 4096, 2048, 1024, 1.f);
    tf32_gemm<false><<<dim3(16, 32), 256, GEMM_SMEM>>>(h0, Wk_s, Kb, nullptr, 4096, 2048, 1024, 1.f);
    tf32_gemm<false><<<dim3(8, 32), 256, GEMM_SMEM>>>(h0, Wv_s, Vb, nullptr, 4096, 1024, 1024, 1.f);
    diff_flash_kernel<<<dim3(16, 64), 256, FA_SMEM_BYTES>>>(Qb, Kb, Vb, Ob, lam, 1);
    tf32_gemm<true><<<dim3(8, 32), 256, GEMM_SMEM>>>(Ob, Wo_s, h1, h0, 4096, 1024, 1024, 1.f);

    // ---- cross attention (non-causal) ----
    tf32_gemm<false><<<dim3(16, 32), 256, GEMM_SMEM>>>(h1, Wq_c, Qb, nullptr, 4096, 2048, 1024, 1.f);
    tf32_gemm<false><<<dim3(16, 32), 256, GEMM_SMEM>>>(enc, Wk_c, Kb, nullptr, 4096, 2048, 1024, 1.f);
    tf32_gemm<false><<<dim3(8, 32), 256, GEMM_SMEM>>>(enc, Wv_c, Vb, nullptr, 4096, 1024, 1024, 1.f);
    diff_flash_kernel<<<dim3(16, 64), 256, FA_SMEM_BYTES>>>(Qb, Kb, Vb, Ob, lam + 16, 0);
    tf32_gemm<false><<<dim3(8, 32), 256, GEMM_SMEM>>>(Ob, Wo_c, h2, nullptr, 4096, 1024, 1024, 2.f);

    // ---- FFN ----
    rmsnorm_kernel<<<4096, 256>>>(h2, grms, h3);
    tf32_gemm<false><<<dim3(32, 32), 256, GEMM_SMEM>>>(h3, W1, G1, nullptr, 4096, 4096, 1024, 1.f);
    tf32_gemm<false><<<dim3(32, 32), 256, GEMM_SMEM>>>(h3, W2, G2, nullptr, 4096, 4096, 1024, 1.f);
    silu_mul_kernel<<<4096, 256>>>(G1, G2, G1, 4096 * 4096 / 4);
    tf32_gemm<true><<<dim3(8, 32), 256, GEMM_SMEM>>>(G1, W3, out, h2, 4096, 1024, 4096, 1.f);
}

// round 3
// speedup vs baseline: 1.8557x; 1.1926x over previous
#include <cuda_runtime.h>
#include <cuda_bf16.h>
#include <cstdint>

// ----------------------------------------------------------------------------
// Problem constants: B=4, T=S=1024, D=1024, H=16, hs=64, Dff=4096
// ----------------------------------------------------------------------------

typedef __nv_bfloat16 bf16;
typedef __nv_bfloat162 bf162;

// f32 scratch
__device__ float g_h0f[4096 * 1024];
__device__ float g_Qb[4096 * 2048];
__device__ float g_Kb[4096 * 2048];
__device__ float g_Vb[4096 * 1024];
__device__ float g_h2[4096 * 1024];
__device__ float g_G1[4096 * 4096];
__device__ float g_G2[4096 * 4096];
__device__ float g_lam[32];

// activation hi/lo planes
__device__ bf16 g_h0h[4096 * 1024], g_h0l[4096 * 1024];
__device__ bf16 g_Obh[4096 * 1024], g_Obl[4096 * 1024];
__device__ bf16 g_h1h[4096 * 1024], g_h1l[4096 * 1024];
__device__ bf16 g_ench[4096 * 1024], g_encl[4096 * 1024];
__device__ bf16 g_h3h[4096 * 1024], g_h3l[4096 * 1024];
__device__ bf16 g_Gh[4096 * 4096],  g_Gl[4096 * 4096];

// weight hi/lo planes
__device__ bf16 g_Wqsh[1024 * 2048], g_Wqsl[1024 * 2048];
__device__ bf16 g_Wksh[1024 * 2048], g_Wksl[1024 * 2048];
__device__ bf16 g_Wvsh[1024 * 1024], g_Wvsl[1024 * 1024];
__device__ bf16 g_Wosh[1024 * 1024], g_Wosl[1024 * 1024];
__device__ bf16 g_Wqch[1024 * 2048], g_Wqcl[1024 * 2048];
__device__ bf16 g_Wkch[1024 * 2048], g_Wkcl[1024 * 2048];
__device__ bf16 g_Wvch[1024 * 1024], g_Wvcl[1024 * 1024];
__device__ bf16 g_Woch[1024 * 1024], g_Wocl[1024 * 1024];
__device__ bf16 g_W1h[1024 * 4096],  g_W1l[1024 * 4096];
__device__ bf16 g_W2h[1024 * 4096],  g_W2l[1024 * 4096];
__device__ bf16 g_W3h[4096 * 1024],  g_W3l[4096 * 1024];

__device__ __forceinline__ void split_bf16(float x, bf16& h, bf16& l) {
    h = __float2bfloat16_rn(x);
    l = __float2bfloat16_rn(x - __bfloat162float(h));
}

// ----------------------------------------------------------------------------
// PTX helpers
// ----------------------------------------------------------------------------
__device__ __forceinline__ void cp16(uint32_t dst, const void* src) {
    asm volatile("cp.async.cg.shared.global [%0], [%1], 16;\n" :: "r"(dst), "l"(src) : "memory");
}
__device__ __forceinline__ void cp_commit() {
    asm volatile("cp.async.commit_group;\n" ::: "memory");
}
__device__ __forceinline__ void ldsm4(uint32_t addr, uint32_t* r) {
    asm volatile("ldmatrix.sync.aligned.m8n8.x4.shared.b16 {%0,%1,%2,%3}, [%4];\n"
                 : "=r"(r[0]), "=r"(r[1]), "=r"(r[2]), "=r"(r[3]) : "r"(addr));
}
__device__ __forceinline__ void ldsm4t(uint32_t addr, uint32_t* r) {
    asm volatile("ldmatrix.sync.aligned.m8n8.x4.trans.shared.b16 {%0,%1,%2,%3}, [%4];\n"
                 : "=r"(r[0]), "=r"(r[1]), "=r"(r[2]), "=r"(r[3]) : "r"(addr));
}
__device__ __forceinline__ void mma_bf16(float* d, const uint32_t* a, uint32_t b0, uint32_t b1) {
    asm volatile(
        "mma.sync.aligned.m16n8k16.row.col.f32.bf16.bf16.f32 "
        "{%0,%1,%2,%3}, {%4,%5,%6,%7}, {%8,%9}, {%0,%1,%2,%3};\n"
        : "+f"(d[0]), "+f"(d[1]), "+f"(d[2]), "+f"(d[3])
        : "r"(a[0]), "r"(a[1]), "r"(a[2]), "r"(a[3]), "r"(b0), "r"(b1));
}

// ----------------------------------------------------------------------------
// convert f32 -> (hi, lo) bf16 planes
// ----------------------------------------------------------------------------
__global__ void convert_kernel(const float* __restrict__ src, bf16* __restrict__ hi,
                               bf16* __restrict__ lo, int n4) {
    int i = blockIdx.x * blockDim.x + threadIdx.x;
    int stride = gridDim.x * blockDim.x;
    for (; i < n4; i += stride) {
        float4 v = ((const float4*)src)[i];
        bf16 h0, l0, h1, l1, h2, l2, h3, l3;
        split_bf16(v.x, h0, l0);
        split_bf16(v.y, h1, l1);
        split_bf16(v.z, h2, l2);
        split_bf16(v.w, h3, l3);
        ((bf162*)hi)[i * 2 + 0] = __halves2bfloat162(h0, h1);
        ((bf162*)hi)[i * 2 + 1] = __halves2bfloat162(h2, h3);
        ((bf162*)lo)[i * 2 + 0] = __halves2bfloat162(l0, l1);
        ((bf162*)lo)[i * 2 + 1] = __halves2bfloat162(l2, l3);
    }
}

// ----------------------------------------------------------------------------
// lambda_h = exp(sum(lq1*lk1)) - exp(sum(lq2*lk2)) + 0.8
// ----------------------------------------------------------------------------
__global__ void lambda_kernel(const float* __restrict__ lq1, const float* __restrict__ lk1,
                              const float* __restrict__ lq2, const float* __restrict__ lk2,
                              float* __restrict__ out) {
    int h = threadIdx.x >> 5;
    int lane = threadIdx.x & 31;
    float s1 = lq1[h * 64 + lane] * lk1[h * 64 + lane] +
               lq1[h * 64 + 32 + lane] * lk1[h * 64 + 32 + lane];
    float s2 = lq2[h * 64 + lane] * lk2[h * 64 + lane] +
               lq2[h * 64 + 32 + lane] * lk2[h * 64 + 32 + lane];
    #pragma unroll
    for (int o = 16; o; o >>= 1) {
        s1 += __shfl_xor_sync(0xffffffffu, s1, o);
        s2 += __shfl_xor_sync(0xffffffffu, s2, o);
    }
    if (lane == 0) out[h] = __expf(s1) - __expf(s2) + 0.8f;
}

// ----------------------------------------------------------------------------
// RMSNorm over last dim (1024). MODE bit0: write f32, bit1: write hi/lo planes.
// ----------------------------------------------------------------------------
template <int MODE>
__global__ void __launch_bounds__(256) rmsnorm_kernel(const float* __restrict__ x,
                                                      const float* __restrict__ g,
                                                      float* __restrict__ yf,
                                                      bf16* __restrict__ yh,
                                                      bf16* __restrict__ yl) {
    int row = blockIdx.x;
    const float4* xr = (const float4*)(x + (size_t)row * 1024);
    float4 v = xr[threadIdx.x];
    float ss = v.x * v.x + v.y * v.y + v.z * v.z + v.w * v.w;
    #pragma unroll
    for (int o = 16; o; o >>= 1) ss += __shfl_xor_sync(0xffffffffu, ss, o);
    __shared__ float red[8];
    int w = threadIdx.x >> 5;
    if ((threadIdx.x & 31) == 0) red[w] = ss;
    __syncthreads();
    if (w == 0) {
        float t = (threadIdx.x < 8) ? red[threadIdx.x] : 0.f;
        #pragma unroll
        for (int o = 4; o; o >>= 1) t += __shfl_xor_sync(0xffffffffu, t, o);
        if (threadIdx.x == 0) red[0] = t;
    }
    __syncthreads();
    float r = rsqrtf(red[0] * (1.0f / 1024.0f) + 1e-6f);
    const float4* gr = (const float4*)g;
    float4 gv = gr[threadIdx.x];
    float4 o4 = make_float4(v.x * r * gv.x, v.y * r * gv.y, v.z * r * gv.z, v.w * r * gv.w);
    if (MODE & 1)
        ((float4*)(yf + (size_t)row * 1024))[threadIdx.x] = o4;
    if (MODE & 2) {
        bf16 h0, l0, h1, l1, h2, l2, h3, l3;
        split_bf16(o4.x, h0, l0);
        split_bf16(o4.y, h1, l1);
        split_bf16(o4.z, h2, l2);
        split_bf16(o4.w, h3, l3);
        size_t p = (size_t)row * 512 + threadIdx.x * 2;
        ((bf162*)yh)[p]     = __halves2bfloat162(h0, h1);
        ((bf162*)yh)[p + 1] = __halves2bfloat162(h2, h3);
        ((bf162*)yl)[p]     = __halves2bfloat162(l0, l1);
        ((bf162*)yl)[p + 1] = __halves2bfloat162(l2, l3);
    }
}

// ----------------------------------------------------------------------------
// bf16x3 split GEMM: C = alpha*(Ah+Al)(Bh+Bl) [+R], A:[M][K], B:[K][N] row-major.
// 128x128x32 tiles, 256 thr, 8 warps (2x4), warp tile 64x32, mma m16n8k16 bf16,
// 3-term split (hh + hl + lh). cp.async 3-stage pipeline, ldmatrix fragments.
// ----------------------------------------------------------------------------
#define STAGES 3
#define STAGE_BYTES 32768
#define GEMM_SMEM (STAGES * STAGE_BYTES)
#define OFF_AH 0
#define OFF_AL 8192
#define OFF_BH 16384
#define OFF_BL 24576

template <bool HAS_RES, bool OUT_PLANES>
__global__ void __launch_bounds__(256) bf16_gemm(
    const bf16* __restrict__ Ah, const bf16* __restrict__ Al,
    const bf16* __restrict__ Bh, const bf16* __restrict__ Bl,
    float* __restrict__ C, bf16* __restrict__ Ch, bf16* __restrict__ Cl,
    const float* __restrict__ R, int M, int N, int K, float alpha) {
    extern __shared__ char smc[];
    const uint32_t smb = (uint32_t)__cvta_generic_to_shared(smc);

    const int tid = threadIdx.x;
    const int lane = tid & 31;
    const int warp = tid >> 5;
    const int wm = warp >> 2, wn = warp & 3;
    const int g = lane >> 2, tg = lane & 3;
    const int row0 = blockIdx.y * 128, col0 = blockIdx.x * 128;

    // cp.async mapping (per thread: 2 chunks per plane)
    const int am0 = tid >> 2, ack0 = tid & 3;            // q = tid
    const int am1 = (tid + 256) >> 2, ack1 = tid & 3;    // q = tid+256
    const int bk0 = tid >> 4, bcn0 = tid & 15;
    const int bk1 = (tid + 256) >> 4, bcn1 = tid & 15;

    auto a_sw = [](int m, int ck) { return (uint32_t)(m * 4 + (ck ^ ((m >> 1) & 3))) * 16; };
    auto b_sw = [](int k, int cn) { return (uint32_t)(k * 16 + (cn ^ (k & 7))) * 16; };

    auto load_stage = [&](int kt, int buf) {
        uint32_t sb = smb + buf * STAGE_BYTES;
        const bf16* srcA0 = Ah + (size_t)(row0 + am0) * K + kt * 32 + ack0 * 8;
        const bf16* srcA1 = Ah + (size_t)(row0 + am1) * K + kt * 32 + ack1 * 8;
        const bf16* srcAl0 = Al + (size_t)(row0 + am0) * K + kt * 32 + ack0 * 8;
        const bf16* srcAl1 = Al + (size_t)(row0 + am1) * K + kt * 32 + ack1 * 8;
        cp16(sb + OFF_AH + a_sw(am0, ack0), srcA0);
        cp16(sb + OFF_AH + a_sw(am1, ack1), srcA1);
        cp16(sb + OFF_AL + a_sw(am0, ack0), srcAl0);
        cp16(sb + OFF_AL + a_sw(am1, ack1), srcAl1);
        const bf16* srcB0 = Bh + (size_t)(kt * 32 + bk0) * N + col0 + bcn0 * 8;
        const bf16* srcB1 = Bh + (size_t)(kt * 32 + bk1) * N + col0 + bcn1 * 8;
        const bf16* srcBl0 = Bl + (size_t)(kt * 32 + bk0) * N + col0 + bcn0 * 8;
        const bf16* srcBl1 = Bl + (size_t)(kt * 32 + bk1) * N + col0 + bcn1 * 8;
        cp16(sb + OFF_BH + b_sw(bk0, bcn0), srcB0);
        cp16(sb + OFF_BH + b_sw(bk1, bcn1), srcB1);
        cp16(sb + OFF_BL + b_sw(bk0, bcn0), srcBl0);
        cp16(sb + OFF_BL + b_sw(bk1, bcn1), srcBl1);
    };

    float acc[4][4][4];
    #pragma unroll
    for (int mi = 0; mi < 4; mi++)
        #pragma unroll
        for (int ni = 0; ni < 4; ni++)
            #pragma unroll
            for (int q = 0; q < 4; q++) acc[mi][ni][q] = 0.f;

    // ldmatrix lane constants
    const int a_mrel = lane & 15, a_cks = lane >> 4;
    const int b_krel = lane & 15, b_cns = lane >> 4;

    const int KT = K >> 5;
    #pragma unroll
    for (int s = 0; s < STAGES - 1; s++) {
        if (s < KT) load_stage(s, s);
        cp_commit();
    }

    for (int kt = 0; kt < KT; kt++) {
        asm volatile("cp.async.wait_group %0;\n" :: "n"(STAGES - 2) : "memory");
        __syncthreads();
        {
            int ls = kt + STAGES - 1;
            if (ls < KT) load_stage(ls, ls % STAGES);
            cp_commit();
        }
        const uint32_t sb = smb + (kt % STAGES) * STAGE_BYTES;
        #pragma unroll
        for (int kh = 0; kh < 2; kh++) {
            uint32_t af_h[4][4], af_l[4][4], bf_h[2][4], bf_l[2][4];
            #pragma unroll
            for (int mi = 0; mi < 4; mi++) {
                int m = wm * 64 + mi * 16 + a_mrel;
                int ck = kh * 2 + a_cks;
                uint32_t off = (uint32_t)(m * 4 + (ck ^ ((m >> 1) & 3))) * 16;
                ldsm4(sb + OFF_AH + off, af_h[mi]);
                ldsm4(sb + OFF_AL + off, af_l[mi]);
            }
            #pragma unroll
            for (int nj = 0; nj < 2; nj++) {
                int k = kh * 16 + b_krel;
                int cn = ((wn * 32 + nj * 16) >> 3) + b_cns;
                uint32_t off = (uint32_t)(k * 16 + (cn ^ (k & 7))) * 16;
                ldsm4t(sb + OFF_BH + off, bf_h[nj]);
                ldsm4t(sb + OFF_BL + off, bf_l[nj]);
            }
            // pass 1: ah*bh
            #pragma unroll
            for (int mi = 0; mi < 4; mi++)
                #pragma unroll
                for (int ni = 0; ni < 4; ni++)
                    mma_bf16(acc[mi][ni], af_h[mi],
                             bf_h[ni >> 1][(ni & 1) * 2], bf_h[ni >> 1][(ni & 1) * 2 + 1]);
            // pass 2: ah*bl
            #pragma unroll
            for (int mi = 0; mi < 4; mi++)
                #pragma unroll
                for (int ni = 0; ni < 4; ni++)
                    mma_bf16(acc[mi][ni], af_h[mi],
                             bf_l[ni >> 1][(ni & 1) * 2], bf_l[ni >> 1][(ni & 1) * 2 + 1]);
            // pass 3: al*bh
            #pragma unroll
            for (int mi = 0; mi < 4; mi++)
                #pragma unroll
                for (int ni = 0; ni < 4; ni++)
                    mma_bf16(acc[mi][ni], af_l[mi],
                             bf_h[ni >> 1][(ni & 1) * 2], bf_h[ni >> 1][(ni & 1) * 2 + 1]);
        }
    }

    // epilogue
    #pragma unroll
    for (int mi = 0; mi < 4; mi++) {
        #pragma unroll
        for (int half = 0; half < 2; half++) {
            int r = row0 + wm * 64 + mi * 16 + g + half * 8;
            #pragma unroll
            for (int ni = 0; ni < 4; ni++) {
                int c = col0 + wn * 32 + ni * 8 + tg * 2;
                float v0 = acc[mi][ni][half * 2 + 0] * alpha;
                float v1 = acc[mi][ni][half * 2 + 1] * alpha;
                if (HAS_RES) {
                    float2 rv = *(const float2*)(R + (size_t)r * N + c);
                    v0 += rv.x; v1 += rv.y;
                }
                if (OUT_PLANES) {
                    bf16 h0, l0, h1, l1;
                    split_bf16(v0, h0, l0);
                    split_bf16(v1, h1, l1);
                    *(bf162*)(Ch + (size_t)r * N + c) = __halves2bfloat162(h0, h1);
                    *(bf162*)(Cl + (size_t)r * N + c) = __halves2bfloat162(l0, l1);
                } else {
                    float2 o;
                    o.x = v0; o.y = v1;
                    *(float2*)(C + (size_t)r * N + c) = o;
                }
            }
        }
    }
}

// ----------------------------------------------------------------------------
// Differential flash attention (fp32 in, hi/lo bf16 plane out).
// ----------------------------------------------------------------------------
#define FA_PITCH 65
#define FA_SMEM_FLOATS (6 * 64 * FA_PITCH + 64 * 64)
#define FA_SMEM_BYTES (FA_SMEM_FLOATS * 4)

__global__ void __launch_bounds__(256) diff_flash_kernel(const float* __restrict__ Q,
                                                         const float* __restrict__ K,
                                                         const float* __restrict__ V,
                                                         bf16* __restrict__ Oh,
                                                         bf16* __restrict__ Ol,
                                                         const float* __restrict__ lam,
                                                         int causal) {
    extern __shared__ float sm[];
    float* Q1t = sm;
    float* Q2t = sm + 1 * 64 * FA_PITCH;
    float* K1t = sm + 2 * 64 * FA_PITCH;
    float* K2t = sm + 3 * 64 * FA_PITCH;
    float* Ps1 = sm + 4 * 64 * FA_PITCH;
    float* Ps2 = sm + 5 * 64 * FA_PITCH;
    float* Vs  = sm + 6 * 64 * FA_PITCH;

    const int tid = threadIdx.x;
    const int tx = tid & 15, ty = tid >> 4;
    const int bh = blockIdx.y;
    const int b = bh >> 4, h = bh & 15;
    const int t0 = blockIdx.x * 64;

    const size_t qbase = ((size_t)b * 1024 + t0) * 2048 + h * 128;
    const size_t kbase0 = ((size_t)b * 1024) * 2048 + h * 128;
    const size_t vbase0 = ((size_t)b * 1024) * 1024 + h * 64;

    #pragma unroll
    for (int it = 0; it < 4; it++) {
        int idx = tid + it * 256;
        int r = idx >> 4;
        int q = (idx & 15) * 4;
        float4 v1 = *(const float4*)(Q + qbase + (size_t)r * 2048 + q);
        float4 v2 = *(const float4*)(Q + qbase + (size_t)r * 2048 + 64 + q);
        Q1t[(q + 0) * FA_PITCH + r] = v1.x;
        Q1t[(q + 1) * FA_PITCH + r] = v1.y;
        Q1t[(q + 2) * FA_PITCH + r] = v1.z;
        Q1t[(q + 3) * FA_PITCH + r] = v1.w;
        Q2t[(q + 0) * FA_PITCH + r] = v2.x;
        Q2t[(q + 1) * FA_PITCH + r] = v2.y;
        Q2t[(q + 2) * FA_PITCH + r] = v2.z;
        Q2t[(q + 3) * FA_PITCH + r] = v2.w;
    }

    float m1[4], l1[4], m2[4], l2[4];
    float o1[4][4], o2[4][4];
    #pragma unroll
    for (int i = 0; i < 4; i++) {
        m1[i] = -1e30f; m2[i] = -1e30f; l1[i] = 0.f; l2[i] = 0.f;
        #pragma unroll
        for (int j = 0; j < 4; j++) { o1[i][j] = 0.f; o2[i][j] = 0.f; }
    }

    const int nS = causal ? (blockIdx.x + 1) : 16;
    const float scale = 0.125f;

    for (int si = 0; si < nS; si++) {
        const size_t kb = kbase0 + (size_t)si * 64 * 2048;
        const size_t vb = vbase0 + (size_t)si * 64 * 1024;
        __syncthreads();
        #pragma unroll
        for (int it = 0; it < 4; it++) {
            int idx = tid + it * 256;
            int r = idx >> 4;
            int q = (idx & 15) * 4;
            float4 kv1 = *(const float4*)(K + kb + (size_t)r * 2048 + q);
            float4 kv2 = *(const float4*)(K + kb + (size_t)r * 2048 + 64 + q);
            float4 vv  = *(const float4*)(V + vb + (size_t)r * 1024 + q);
            K1t[(q + 0) * FA_PITCH + r] = kv1.x;
            K1t[(q + 1) * FA_PITCH + r] = kv1.y;
            K1t[(q + 2) * FA_PITCH + r] = kv1.z;
            K1t[(q + 3) * FA_PITCH + r] = kv1.w;
            K2t[(q + 0) * FA_PITCH + r] = kv2.x;
            K2t[(q + 1) * FA_PITCH + r] = kv2.y;
            K2t[(q + 2) * FA_PITCH + r] = kv2.z;
            K2t[(q + 3) * FA_PITCH + r] = kv2.w;
            *(float4*)&Vs[r * 64 + q] = vv;
        }
        __syncthreads();

        float s1r[4][4], s2r[4][4];
        #pragma unroll
        for (int i = 0; i < 4; i++)
            #pragma unroll
            for (int j = 0; j < 4; j++) { s1r[i][j] = 0.f; s2r[i][j] = 0.f; }

        #pragma unroll 4
        for (int d = 0; d < 64; d++) {
            float a1[4], a2[4], b1[4], b2[4];
            #pragma unroll
            for (int i = 0; i < 4; i++) {
                a1[i] = Q1t[d * FA_PITCH + ty + 16 * i];
                a2[i] = Q2t[d * FA_PITCH + ty + 16 * i];
            }
            #pragma unroll
            for (int j = 0; j < 4; j++) {
                b1[j] = K1t[d * FA_PITCH + tx + 16 * j];
                b2[j] = K2t[d * FA_PITCH + tx + 16 * j];
            }
            #pragma unroll
            for (int i = 0; i < 4; i++)
                #pragma unroll
                for (int j = 0; j < 4; j++) {
                    s1r[i][j] = fmaf(a1[i], b1[j], s1r[i][j]);
                    s2r[i][j] = fmaf(a2[i], b2[j], s2r[i][j]);
                }
        }

        const bool diag = (causal && si == (int)blockIdx.x);
        #pragma unroll
        for (int i = 0; i < 4; i++) {
            int rr = ty + 16 * i;
            #pragma unroll
            for (int j = 0; j < 4; j++) {
                float v1 = s1r[i][j] * scale;
                float v2 = s2r[i][j] * scale;
                if (diag && (tx + 16 * j) > rr) { v1 = -1e9f; v2 = -1e9f; }
                s1r[i][j] = v1;
                s2r[i][j] = v2;
            }
        }

        #pragma unroll
        for (int i = 0; i < 4; i++) {
            {
                float mx = fmaxf(fmaxf(s1r[i][0], s1r[i][1]), fmaxf(s1r[i][2], s1r[i][3]));
                mx = fmaxf(mx, __shfl_xor_sync(0xffffffffu, mx, 8));
                mx = fmaxf(mx, __shfl_xor_sync(0xffffffffu, mx, 4));
                mx = fmaxf(mx, __shfl_xor_sync(0xffffffffu, mx, 2));
                mx = fmaxf(mx, __shfl_xor_sync(0xffffffffu, mx, 1));
                float mn = fmaxf(m1[i], mx);
                float corr = __expf(m1[i] - mn);
                float rs = 0.f;
                #pragma unroll
                for (int j = 0; j < 4; j++) {
                    float p = __expf(s1r[i][j] - mn);
                    s1r[i][j] = p;
                    rs += p;
                }
                rs += __shfl_xor_sync(0xffffffffu, rs, 8);
                rs += __shfl_xor_sync(0xffffffffu, rs, 4);
                rs += __shfl_xor_sync(0xffffffffu, rs, 2);
                rs += __shfl_xor_sync(0xffffffffu, rs, 1);
                l1[i] = l1[i] * corr + rs;
                m1[i] = mn;
                #pragma unroll
                for (int j = 0; j < 4; j++) o1[i][j] *= corr;
                #pragma unroll
                for (int j = 0; j < 4; j++)
                    Ps1[(tx + 16 * j) * FA_PITCH + ty + 16 * i] = s1r[i][j];
            }
            {
                float mx = fmaxf(fmaxf(s2r[i][0], s2r[i][1]), fmaxf(s2r[i][2], s2r[i][3]));
                mx = fmaxf(mx, __shfl_xor_sync(0xffffffffu, mx, 8));
                mx = fmaxf(mx, __shfl_xor_sync(0xffffffffu, mx, 4));
                mx = fmaxf(mx, __shfl_xor_sync(0xffffffffu, mx, 2));
                mx = fmaxf(mx, __shfl_xor_sync(0xffffffffu, mx, 1));
                float mn = fmaxf(m2[i], mx);
                float corr = __expf(m2[i] - mn);
                float rs = 0.f;
                #pragma unroll
                for (int j = 0; j < 4; j++) {
                    float p = __expf(s2r[i][j] - mn);
                    s2r[i][j] = p;
                    rs += p;
                }
                rs += __shfl_xor_sync(0xffffffffu, rs, 8);
                rs += __shfl_xor_sync(0xffffffffu, rs, 4);
                rs += __shfl_xor_sync(0xffffffffu, rs, 2);
                rs += __shfl_xor_sync(0xffffffffu, rs, 1);
                l2[i] = l2[i] * corr + rs;
                m2[i] = mn;
                #pragma unroll
                for (int j = 0; j < 4; j++) o2[i][j] *= corr;
                #pragma unroll
                for (int j = 0; j < 4; j++)
                    Ps2[(tx + 16 * j) * FA_PITCH + ty + 16 * i] = s2r[i][j];
            }
        }
        __syncthreads();

        #pragma unroll 4
        for (int s = 0; s < 64; s++) {
            float a1v[4], a2v[4], bv[4];
            #pragma unroll
            for (int i = 0; i < 4; i++) {
                a1v[i] = Ps1[s * FA_PITCH + ty + 16 * i];
                a2v[i] = Ps2[s * FA_PITCH + ty + 16 * i];
            }
            #pragma unroll
            for (int j = 0; j < 4; j++) bv[j] = Vs[s * 64 + tx + 16 * j];
            #pragma unroll
            for (int i = 0; i < 4; i++)
                #pragma unroll
                for (int j = 0; j < 4; j++) {
                    o1[i][j] = fmaf(a1v[i], bv[j], o1[i][j]);
                    o2[i][j] = fmaf(a2v[i], bv[j], o2[i][j]);
                }
        }
    }

    const float lv = lam[h];
    const size_t obase = ((size_t)b * 1024 + t0) * 1024 + h * 64;
    #pragma unroll
    for (int i = 0; i < 4; i++) {
        float inv1 = 1.f / l1[i];
        float inv2 = 1.f / l2[i];
        float of[4];
        float ss = 0.f;
        #pragma unroll
        for (int j = 0; j < 4; j++) {
            of[j] = o1[i][j] * inv1 - lv * (o2[i][j] * inv2);
            ss += of[j] * of[j];
        }
        ss += __shfl_xor_sync(0xffffffffu, ss, 8);
        ss += __shfl_xor_sync(0xffffffffu, ss, 4);
        ss += __shfl_xor_sync(0xffffffffu, ss, 2);
        ss += __shfl_xor_sync(0xffffffffu, ss, 1);
        float rn = rsqrtf(ss * (1.0f / 64.0f) + 1e-6f) * 0.2f;
        #pragma unroll
        for (int j = 0; j < 4; j++) {
            float val = of[j] * rn;
            size_t idx = obase + (size_t)(ty + 16 * i) * 1024 + tx + 16 * j;
            bf16 hv, lvv;
            split_bf16(val, hv, lvv);
            Oh[idx] = hv;
            Ol[idx] = lvv;
        }
    }
}

// ----------------------------------------------------------------------------
// y = silu(g1) * g2 -> hi/lo planes
// ----------------------------------------------------------------------------
__global__ void silu_mul_kernel(const float* __restrict__ g1, const float* __restrict__ g2,
                                bf16* __restrict__ yh, bf16* __restrict__ yl, int n4) {
    int i = blockIdx.x * blockDim.x + threadIdx.x;
    int stride = gridDim.x * blockDim.x;
    for (; i < n4; i += stride) {
        float4 a = ((const float4*)g1)[i];
        float4 b = ((const float4*)g2)[i];
        float4 r;
        r.x = a.x / (1.f + __expf(-a.x)) * b.x;
        r.y = a.y / (1.f + __expf(-a.y)) * b.y;
        r.z = a.z / (1.f + __expf(-a.z)) * b.z;
        r.w = a.w / (1.f + __expf(-a.w)) * b.w;
        bf16 h0, l0, h1, l1, h2, l2, h3, l3;
        split_bf16(r.x, h0, l0);
        split_bf16(r.y, h1, l1);
        split_bf16(r.z, h2, l2);
        split_bf16(r.w, h3, l3);
        ((bf162*)yh)[i * 2 + 0] = __halves2bfloat162(h0, h1);
        ((bf162*)yh)[i * 2 + 1] = __halves2bfloat162(h2, h3);
        ((bf162*)yl)[i * 2 + 0] = __halves2bfloat162(l0, l1);
        ((bf162*)yl)[i * 2 + 1] = __halves2bfloat162(l2, l3);
    }
}

// ----------------------------------------------------------------------------
// kernel_launch
// ----------------------------------------------------------------------------
#define SYM(v, s) cudaGetSymbolAddress((void**)&v, s)

extern "C" void kernel_launch(void* const* d_in, const int* in_sizes, int n_in,
                              void* d_out, int out_size) {
    const float* x     = (const float*)d_in[0];
    const float* enc   = (const float*)d_in[1];
    const float* Wq_s  = (const float*)d_in[2];
    const float* Wk_s  = (const float*)d_in[3];
    const float* Wv_s  = (const float*)d_in[4];
    const float* Wo_s  = (const float*)d_in[5];
    const float* lq1_s = (const float*)d_in[6];
    const float* lk1_s = (const float*)d_in[7];
    const float* lq2_s = (const float*)d_in[8];
    const float* lk2_s = (const float*)d_in[9];
    const float* Wq_c  = (const float*)d_in[10];
    const float* Wk_c  = (const float*)d_in[11];
    const float* Wv_c  = (const float*)d_in[12];
    const float* Wo_c  = (const float*)d_in[13];
    const float* lq1_c = (const float*)d_in[14];
    const float* lk1_c = (const float*)d_in[15];
    const float* lq2_c = (const float*)d_in[16];
    const float* lk2_c = (const float*)d_in[17];
    const float* grms  = (const float*)d_in[18];
    const float* W1    = (const float*)d_in[19];
    const float* W2    = (const float*)d_in[20];
    const float* W3    = (const float*)d_in[21];
    float* out = (float*)d_out;

    float *h0f, *Qb, *Kb, *Vb, *h2, *G1, *G2, *lam;
    SYM(h0f, g_h0f); SYM(Qb, g_Qb); SYM(Kb, g_Kb); SYM(Vb, g_Vb);
    SYM(h2, g_h2); SYM(G1, g_G1); SYM(G2, g_G2); SYM(lam, g_lam);

    bf16 *h0h, *h0l, *Obh, *Obl, *h1h, *h1l, *ench, *encl, *h3h, *h3l, *Gh, *Gl;
    SYM(h0h, g_h0h); SYM(h0l, g_h0l); SYM(Obh, g_Obh); SYM(Obl, g_Obl);
    SYM(h1h, g_h1h); SYM(h1l, g_h1l); SYM(ench, g_ench); SYM(encl, g_encl);
    SYM(h3h, g_h3h); SYM(h3l, g_h3l); SYM(Gh, g_Gh); SYM(Gl, g_Gl);

    bf16 *Wqsh, *Wqsl, *Wksh, *Wksl, *Wvsh, *Wvsl, *Wosh, *Wosl;
    bf16 *Wqch, *Wqcl, *Wkch, *Wkcl, *Wvch, *Wvcl, *Woch, *Wocl;
    bf16 *W1h, *W1l, *W2h, *W2l, *W3h, *W3l;
    SYM(Wqsh, g_Wqsh); SYM(Wqsl, g_Wqsl); SYM(Wksh, g_Wksh); SYM(Wksl, g_Wksl);
    SYM(Wvsh, g_Wvsh); SYM(Wvsl, g_Wvsl); SYM(Wosh, g_Wosh); SYM(Wosl, g_Wosl);
    SYM(Wqch, g_Wqch); SYM(Wqcl, g_Wqcl); SYM(Wkch, g_Wkch); SYM(Wkcl, g_Wkcl);
    SYM(Wvch, g_Wvch); SYM(Wvcl, g_Wvcl); SYM(Woch, g_Woch); SYM(Wocl, g_Wocl);
    SYM(W1h, g_W1h); SYM(W1l, g_W1l); SYM(W2h, g_W2h); SYM(W2l, g_W2l);
    SYM(W3h, g_W3h); SYM(W3l, g_W3l);

    cudaFuncSetAttribute(diff_flash_kernel, cudaFuncAttributeMaxDynamicSharedMemorySize,
                         FA_SMEM_BYTES);
    cudaFuncSetAttribute(bf16_gemm<false, false>, cudaFuncAttributeMaxDynamicSharedMemorySize,
                         GEMM_SMEM);
    cudaFuncSetAttribute(bf16_gemm<true, false>, cudaFuncAttributeMaxDynamicSharedMemorySize,
                         GEMM_SMEM);
    cudaFuncSetAttribute(bf16_gemm<true, true>, cudaFuncAttributeMaxDynamicSharedMemorySize,
                         GEMM_SMEM);

    lambda_kernel<<<1, 512>>>(lq1_s, lk1_s, lq2_s, lk2_s, lam);
    lambda_kernel<<<1, 512>>>(lq1_c, lk1_c, lq2_c, lk2_c, lam + 16);

    // weight + encoder splits
    convert_kernel<<<2048, 256>>>(Wq_s, Wqsh, Wqsl, 1024 * 2048 / 4);
    convert_kernel<<<2048, 256>>>(Wk_s, Wksh, Wksl, 1024 * 2048 / 4);
    convert_kernel<<<1024, 256>>>(Wv_s, Wvsh, Wvsl, 1024 * 1024 / 4);
    convert_kernel<<<1024, 256>>>(Wo_s, Wosh, Wosl, 1024 * 1024 / 4);
    convert_kernel<<<2048, 256>>>(Wq_c, Wqch, Wqcl, 1024 * 2048 / 4);
    convert_kernel<<<2048, 256>>>(Wk_c, Wkch, Wkcl, 1024 * 2048 / 4);
    convert_kernel<<<1024, 256>>>(Wv_c, Wvch, Wvcl, 1024 * 1024 / 4);
    convert_kernel<<<1024, 256>>>(Wo_c, Woch, Wocl, 1024 * 1024 / 4);
    convert_kernel<<<4096, 256>>>(W1, W1h, W1l, 1024 * 4096 / 4);
    convert_kernel<<<4096, 256>>>(W2, W2h, W2l, 1024 * 4096 / 4);
    convert_kernel<<<4096, 256>>>(W3, W3h, W3l, 4096 * 1024 / 4);
    convert_kernel<<<4096, 256>>>(enc, ench, encl, 4096 * 1024 / 4);

    // h0 = rmsnorm(x): f32 + planes
    rmsnorm_kernel<3><<<4096, 256>>>(x, grms, h0f, h0h, h0l);

    // ---- self attention (causal) ----
    bf16_gemm<false, false><<<dim3(16, 32), 256, GEMM_SMEM>>>(
        h0h, h0l, Wqsh, Wqsl, Qb, nullptr, nullptr, nullptr, 4096, 2048, 1024, 1.f);
    bf16_gemm<false, false><<<dim3(16, 32), 256, GEMM_SMEM>>>(
        h0h, h0l, Wksh, Wksl, Kb, nullptr, nullptr, nullptr, 4096, 2048, 1024, 1.f);
    bf16_gemm<false, false><<<dim3(8, 32), 256, GEMM_SMEM>>>(
        h0h, h0l, Wvsh, Wvsl, Vb, nullptr, nullptr, nullptr, 4096, 1024, 1024, 1.f);
    diff_flash_kernel<<<dim3(16, 64), 256, FA_SMEM_BYTES>>>(Qb, Kb, Vb, Obh, Obl, lam, 1);
    // h1 = Ob @ Wo_s + h0  (planes only)
    bf16_gemm<true, true><<<dim3(8, 32), 256, GEMM_SMEM>>>(
        Obh, Obl, Wosh, Wosl, nullptr, h1h, h1l, h0f, 4096, 1024, 1024, 1.f);

    // ---- cross attention (non-causal) ----
    bf16_gemm<false, false><<<dim3(16, 32), 256, GEMM_SMEM>>>(
        h1h, h1l, Wqch, Wqcl, Qb, nullptr, nullptr, nullptr, 4096, 2048, 1024, 1.f);
    bf16_gemm<false, false><<<dim3(16, 32), 256, GEMM_SMEM>>>(
        ench, encl, Wkch, Wkcl, Kb, nullptr, nullptr, nullptr, 4096, 2048, 1024, 1.f);
    bf16_gemm<false, false><<<dim3(8, 32), 256, GEMM_SMEM>>>(
        ench, encl, Wvch, Wvcl, Vb, nullptr, nullptr, nullptr, 4096, 1024, 1024, 1.f);
    diff_flash_kernel<<<dim3(16, 64), 256, FA_SMEM_BYTES>>>(Qb, Kb, Vb, Obh, Obl, lam + 16, 0);
    // h2 = 2 * (Ob @ Wo_c)  (f32)
    bf16_gemm<false, false><<<dim3(8, 32), 256, GEMM_SMEM>>>(
        Obh, Obl, Woch, Wocl, h2, nullptr, nullptr, nullptr, 4096, 1024, 1024, 2.f);

    // ---- FFN ----
    rmsnorm_kernel<2><<<4096, 256>>>(h2, grms, nullptr, h3h, h3l);
    bf16_gemm<false, false><<<dim3(32, 32), 256, GEMM_SMEM>>>(
        h3h, h3l, W1h, W1l, G1, nullptr, nullptr, nullptr, 4096, 4096, 1024, 1.f);
    bf16_gemm<false, false><<<dim3(32, 32), 256, GEMM_SMEM>>>(
        h3h, h3l, W2h, W2l, G2, nullptr, nullptr, nullptr, 4096, 4096, 1024, 1.f);
    silu_mul_kernel<<<4096, 256>>>(G1, G2, Gh, Gl, 4096 * 4096 / 4);
    bf16_gemm<true, false><<<dim3(8, 32), 256, GEMM_SMEM>>>(
        Gh, Gl, W3h, W3l, out, nullptr, nullptr, h2, 4096, 1024, 4096, 1.f);
}

// round 4
// speedup vs baseline: 2.8736x; 1.5486x over previous
#include <cuda_runtime.h>
#include <cuda_bf16.h>
#include <cstdint>

// ----------------------------------------------------------------------------
// Problem constants: B=4, T=S=1024, D=1024, H=16, hs=64, Dff=4096
// ----------------------------------------------------------------------------

typedef __nv_bfloat16 bf16;
typedef __nv_bfloat162 bf162;

// f32 scratch
__device__ float g_h0f[4096 * 1024];
__device__ float g_h2[4096 * 1024];
__device__ float g_G1[4096 * 4096];
__device__ float g_G2[4096 * 4096];
__device__ float g_lam[32];

// activation hi/lo planes
__device__ bf16 g_h0h[4096 * 1024], g_h0l[4096 * 1024];
__device__ bf16 g_Qh[4096 * 2048],  g_Ql[4096 * 2048];
__device__ bf16 g_Kh[4096 * 2048],  g_Kl[4096 * 2048];
__device__ bf16 g_Vh[4096 * 1024],  g_Vl[4096 * 1024];
__device__ bf16 g_Obh[4096 * 1024], g_Obl[4096 * 1024];
__device__ bf16 g_h1h[4096 * 1024], g_h1l[4096 * 1024];
__device__ bf16 g_ench[4096 * 1024], g_encl[4096 * 1024];
__device__ bf16 g_h3h[4096 * 1024], g_h3l[4096 * 1024];
__device__ bf16 g_Gh[4096 * 4096],  g_Gl[4096 * 4096];

// weight hi/lo planes
__device__ bf16 g_Wqsh[1024 * 2048], g_Wqsl[1024 * 2048];
__device__ bf16 g_Wksh[1024 * 2048], g_Wksl[1024 * 2048];
__device__ bf16 g_Wvsh[1024 * 1024], g_Wvsl[1024 * 1024];
__device__ bf16 g_Wosh[1024 * 1024], g_Wosl[1024 * 1024];
__device__ bf16 g_Wqch[1024 * 2048], g_Wqcl[1024 * 2048];
__device__ bf16 g_Wkch[1024 * 2048], g_Wkcl[1024 * 2048];
__device__ bf16 g_Wvch[1024 * 1024], g_Wvcl[1024 * 1024];
__device__ bf16 g_Woch[1024 * 1024], g_Wocl[1024 * 1024];
__device__ bf16 g_W1h[1024 * 4096],  g_W1l[1024 * 4096];
__device__ bf16 g_W2h[1024 * 4096],  g_W2l[1024 * 4096];
__device__ bf16 g_W3h[4096 * 1024],  g_W3l[4096 * 1024];

__device__ __forceinline__ void split_bf16(float x, bf16& h, bf16& l) {
    h = __float2bfloat16_rn(x);
    l = __float2bfloat16_rn(x - __bfloat162float(h));
}
__device__ __forceinline__ uint32_t pack2(bf16 a, bf16 b) {
    bf162 t = __halves2bfloat162(a, b);
    return *reinterpret_cast<uint32_t*>(&t);
}
__device__ __forceinline__ void split_pack(float x, float y, uint32_t& hi, uint32_t& lo) {
    bf16 hx = __float2bfloat16_rn(x), hy = __float2bfloat16_rn(y);
    bf16 lx = __float2bfloat16_rn(x - __bfloat162float(hx));
    bf16 ly = __float2bfloat16_rn(y - __bfloat162float(hy));
    hi = pack2(hx, hy);
    lo = pack2(lx, ly);
}

// ----------------------------------------------------------------------------
// PTX helpers
// ----------------------------------------------------------------------------
__device__ __forceinline__ void cp16(uint32_t dst, const void* src) {
    asm volatile("cp.async.cg.shared.global [%0], [%1], 16;\n" :: "r"(dst), "l"(src) : "memory");
}
__device__ __forceinline__ void cp_commit() {
    asm volatile("cp.async.commit_group;\n" ::: "memory");
}
__device__ __forceinline__ void ldsm4(uint32_t addr, uint32_t* r) {
    asm volatile("ldmatrix.sync.aligned.m8n8.x4.shared.b16 {%0,%1,%2,%3}, [%4];\n"
                 : "=r"(r[0]), "=r"(r[1]), "=r"(r[2]), "=r"(r[3]) : "r"(addr));
}
__device__ __forceinline__ void ldsm4t(uint32_t addr, uint32_t* r) {
    asm volatile("ldmatrix.sync.aligned.m8n8.x4.trans.shared.b16 {%0,%1,%2,%3}, [%4];\n"
                 : "=r"(r[0]), "=r"(r[1]), "=r"(r[2]), "=r"(r[3]) : "r"(addr));
}
__device__ __forceinline__ void mma_bf16(float* d, const uint32_t* a, uint32_t b0, uint32_t b1) {
    asm volatile(
        "mma.sync.aligned.m16n8k16.row.col.f32.bf16.bf16.f32 "
        "{%0,%1,%2,%3}, {%4,%5,%6,%7}, {%8,%9}, {%0,%1,%2,%3};\n"
        : "+f"(d[0]), "+f"(d[1]), "+f"(d[2]), "+f"(d[3])
        : "r"(a[0]), "r"(a[1]), "r"(a[2]), "r"(a[3]), "r"(b0), "r"(b1));
}

// ----------------------------------------------------------------------------
// convert f32 -> (hi, lo) bf16 planes
// ----------------------------------------------------------------------------
__global__ void convert_kernel(const float* __restrict__ src, bf16* __restrict__ hi,
                               bf16* __restrict__ lo, int n4) {
    int i = blockIdx.x * blockDim.x + threadIdx.x;
    int stride = gridDim.x * blockDim.x;
    for (; i < n4; i += stride) {
        float4 v = ((const float4*)src)[i];
        bf16 h0, l0, h1, l1, h2, l2, h3, l3;
        split_bf16(v.x, h0, l0);
        split_bf16(v.y, h1, l1);
        split_bf16(v.z, h2, l2);
        split_bf16(v.w, h3, l3);
        ((bf162*)hi)[i * 2 + 0] = __halves2bfloat162(h0, h1);
        ((bf162*)hi)[i * 2 + 1] = __halves2bfloat162(h2, h3);
        ((bf162*)lo)[i * 2 + 0] = __halves2bfloat162(l0, l1);
        ((bf162*)lo)[i * 2 + 1] = __halves2bfloat162(l2, l3);
    }
}

// ----------------------------------------------------------------------------
// lambda_h
// ----------------------------------------------------------------------------
__global__ void lambda_kernel(const float* __restrict__ lq1, const float* __restrict__ lk1,
                              const float* __restrict__ lq2, const float* __restrict__ lk2,
                              float* __restrict__ out) {
    int h = threadIdx.x >> 5;
    int lane = threadIdx.x & 31;
    float s1 = lq1[h * 64 + lane] * lk1[h * 64 + lane] +
               lq1[h * 64 + 32 + lane] * lk1[h * 64 + 32 + lane];
    float s2 = lq2[h * 64 + lane] * lk2[h * 64 + lane] +
               lq2[h * 64 + 32 + lane] * lk2[h * 64 + 32 + lane];
    #pragma unroll
    for (int o = 16; o; o >>= 1) {
        s1 += __shfl_xor_sync(0xffffffffu, s1, o);
        s2 += __shfl_xor_sync(0xffffffffu, s2, o);
    }
    if (lane == 0) out[h] = __expf(s1) - __expf(s2) + 0.8f;
}

// ----------------------------------------------------------------------------
// RMSNorm. MODE bit0: write f32, bit1: write hi/lo planes.
// ----------------------------------------------------------------------------
template <int MODE>
__global__ void __launch_bounds__(256) rmsnorm_kernel(const float* __restrict__ x,
                                                      const float* __restrict__ g,
                                                      float* __restrict__ yf,
                                                      bf16* __restrict__ yh,
                                                      bf16* __restrict__ yl) {
    int row = blockIdx.x;
    const float4* xr = (const float4*)(x + (size_t)row * 1024);
    float4 v = xr[threadIdx.x];
    float ss = v.x * v.x + v.y * v.y + v.z * v.z + v.w * v.w;
    #pragma unroll
    for (int o = 16; o; o >>= 1) ss += __shfl_xor_sync(0xffffffffu, ss, o);
    __shared__ float red[8];
    int w = threadIdx.x >> 5;
    if ((threadIdx.x & 31) == 0) red[w] = ss;
    __syncthreads();
    if (w == 0) {
        float t = (threadIdx.x < 8) ? red[threadIdx.x] : 0.f;
        #pragma unroll
        for (int o = 4; o; o >>= 1) t += __shfl_xor_sync(0xffffffffu, t, o);
        if (threadIdx.x == 0) red[0] = t;
    }
    __syncthreads();
    float r = rsqrtf(red[0] * (1.0f / 1024.0f) + 1e-6f);
    const float4* gr = (const float4*)g;
    float4 gv = gr[threadIdx.x];
    float4 o4 = make_float4(v.x * r * gv.x, v.y * r * gv.y, v.z * r * gv.z, v.w * r * gv.w);
    if (MODE & 1)
        ((float4*)(yf + (size_t)row * 1024))[threadIdx.x] = o4;
    if (MODE & 2) {
        bf16 h0, l0, h1, l1, h2, l2, h3, l3;
        split_bf16(o4.x, h0, l0);
        split_bf16(o4.y, h1, l1);
        split_bf16(o4.z, h2, l2);
        split_bf16(o4.w, h3, l3);
        size_t p = (size_t)row * 512 + threadIdx.x * 2;
        ((bf162*)yh)[p]     = __halves2bfloat162(h0, h1);
        ((bf162*)yh)[p + 1] = __halves2bfloat162(h2, h3);
        ((bf162*)yl)[p]     = __halves2bfloat162(l0, l1);
        ((bf162*)yl)[p + 1] = __halves2bfloat162(l2, l3);
    }
}

// ----------------------------------------------------------------------------
// bf16x3 split GEMM (unchanged from R3, verified).
// ----------------------------------------------------------------------------
#define STAGES 3
#define STAGE_BYTES 32768
#define GEMM_SMEM (STAGES * STAGE_BYTES)
#define OFF_AH 0
#define OFF_AL 8192
#define OFF_BH 16384
#define OFF_BL 24576

template <bool HAS_RES, bool OUT_PLANES>
__global__ void __launch_bounds__(256) bf16_gemm(
    const bf16* __restrict__ Ah, const bf16* __restrict__ Al,
    const bf16* __restrict__ Bh, const bf16* __restrict__ Bl,
    float* __restrict__ C, bf16* __restrict__ Ch, bf16* __restrict__ Cl,
    const float* __restrict__ R, int M, int N, int K, float alpha) {
    extern __shared__ char smc[];
    const uint32_t smb = (uint32_t)__cvta_generic_to_shared(smc);

    const int tid = threadIdx.x;
    const int lane = tid & 31;
    const int warp = tid >> 5;
    const int wm = warp >> 2, wn = warp & 3;
    const int g = lane >> 2, tg = lane & 3;
    const int row0 = blockIdx.y * 128, col0 = blockIdx.x * 128;

    const int am0 = tid >> 2, ack0 = tid & 3;
    const int am1 = (tid + 256) >> 2, ack1 = tid & 3;
    const int bk0 = tid >> 4, bcn0 = tid & 15;
    const int bk1 = (tid + 256) >> 4, bcn1 = tid & 15;

    auto a_sw = [](int m, int ck) { return (uint32_t)(m * 4 + (ck ^ ((m >> 1) & 3))) * 16; };
    auto b_sw = [](int k, int cn) { return (uint32_t)(k * 16 + (cn ^ (k & 7))) * 16; };

    auto load_stage = [&](int kt, int buf) {
        uint32_t sb = smb + buf * STAGE_BYTES;
        cp16(sb + OFF_AH + a_sw(am0, ack0), Ah + (size_t)(row0 + am0) * K + kt * 32 + ack0 * 8);
        cp16(sb + OFF_AH + a_sw(am1, ack1), Ah + (size_t)(row0 + am1) * K + kt * 32 + ack1 * 8);
        cp16(sb + OFF_AL + a_sw(am0, ack0), Al + (size_t)(row0 + am0) * K + kt * 32 + ack0 * 8);
        cp16(sb + OFF_AL + a_sw(am1, ack1), Al + (size_t)(row0 + am1) * K + kt * 32 + ack1 * 8);
        cp16(sb + OFF_BH + b_sw(bk0, bcn0), Bh + (size_t)(kt * 32 + bk0) * N + col0 + bcn0 * 8);
        cp16(sb + OFF_BH + b_sw(bk1, bcn1), Bh + (size_t)(kt * 32 + bk1) * N + col0 + bcn1 * 8);
        cp16(sb + OFF_BL + b_sw(bk0, bcn0), Bl + (size_t)(kt * 32 + bk0) * N + col0 + bcn0 * 8);
        cp16(sb + OFF_BL + b_sw(bk1, bcn1), Bl + (size_t)(kt * 32 + bk1) * N + col0 + bcn1 * 8);
    };

    float acc[4][4][4];
    #pragma unroll
    for (int mi = 0; mi < 4; mi++)
        #pragma unroll
        for (int ni = 0; ni < 4; ni++)
            #pragma unroll
            for (int q = 0; q < 4; q++) acc[mi][ni][q] = 0.f;

    const int a_mrel = lane & 15, a_cks = lane >> 4;
    const int b_krel = lane & 15, b_cns = lane >> 4;

    const int KT = K >> 5;
    #pragma unroll
    for (int s = 0; s < STAGES - 1; s++) {
        if (s < KT) load_stage(s, s);
        cp_commit();
    }

    for (int kt = 0; kt < KT; kt++) {
        asm volatile("cp.async.wait_group %0;\n" :: "n"(STAGES - 2) : "memory");
        __syncthreads();
        {
            int ls = kt + STAGES - 1;
            if (ls < KT) load_stage(ls, ls % STAGES);
            cp_commit();
        }
        const uint32_t sb = smb + (kt % STAGES) * STAGE_BYTES;
        #pragma unroll
        for (int kh = 0; kh < 2; kh++) {
            uint32_t af_h[4][4], af_l[4][4], bf_h[2][4], bf_l[2][4];
            #pragma unroll
            for (int mi = 0; mi < 4; mi++) {
                int m = wm * 64 + mi * 16 + a_mrel;
                int ck = kh * 2 + a_cks;
                uint32_t off = (uint32_t)(m * 4 + (ck ^ ((m >> 1) & 3))) * 16;
                ldsm4(sb + OFF_AH + off, af_h[mi]);
                ldsm4(sb + OFF_AL + off, af_l[mi]);
            }
            #pragma unroll
            for (int nj = 0; nj < 2; nj++) {
                int k = kh * 16 + b_krel;
                int cn = ((wn * 32 + nj * 16) >> 3) + b_cns;
                uint32_t off = (uint32_t)(k * 16 + (cn ^ (k & 7))) * 16;
                ldsm4t(sb + OFF_BH + off, bf_h[nj]);
                ldsm4t(sb + OFF_BL + off, bf_l[nj]);
            }
            #pragma unroll
            for (int mi = 0; mi < 4; mi++)
                #pragma unroll
                for (int ni = 0; ni < 4; ni++)
                    mma_bf16(acc[mi][ni], af_h[mi],
                             bf_h[ni >> 1][(ni & 1) * 2], bf_h[ni >> 1][(ni & 1) * 2 + 1]);
            #pragma unroll
            for (int mi = 0; mi < 4; mi++)
                #pragma unroll
                for (int ni = 0; ni < 4; ni++)
                    mma_bf16(acc[mi][ni], af_h[mi],
                             bf_l[ni >> 1][(ni & 1) * 2], bf_l[ni >> 1][(ni & 1) * 2 + 1]);
            #pragma unroll
            for (int mi = 0; mi < 4; mi++)
                #pragma unroll
                for (int ni = 0; ni < 4; ni++)
                    mma_bf16(acc[mi][ni], af_l[mi],
                             bf_h[ni >> 1][(ni & 1) * 2], bf_h[ni >> 1][(ni & 1) * 2 + 1]);
        }
    }

    #pragma unroll
    for (int mi = 0; mi < 4; mi++) {
        #pragma unroll
        for (int half = 0; half < 2; half++) {
            int r = row0 + wm * 64 + mi * 16 + g + half * 8;
            #pragma unroll
            for (int ni = 0; ni < 4; ni++) {
                int c = col0 + wn * 32 + ni * 8 + tg * 2;
                float v0 = acc[mi][ni][half * 2 + 0] * alpha;
                float v1 = acc[mi][ni][half * 2 + 1] * alpha;
                if (HAS_RES) {
                    float2 rv = *(const float2*)(R + (size_t)r * N + c);
                    v0 += rv.x; v1 += rv.y;
                }
                if (OUT_PLANES) {
                    bf16 h0, l0, h1, l1;
                    split_bf16(v0, h0, l0);
                    split_bf16(v1, h1, l1);
                    *(bf162*)(Ch + (size_t)r * N + c) = __halves2bfloat162(h0, h1);
                    *(bf162*)(Cl + (size_t)r * N + c) = __halves2bfloat162(l0, l1);
                } else {
                    float2 o;
                    o.x = v0; o.y = v1;
                    *(float2*)(C + (size_t)r * N + c) = o;
                }
            }
        }
    }
}

// ----------------------------------------------------------------------------
// Tensor-core differential flash attention.
// Block: 128 thr (4 warps), 64 q-rows, one (b,h). Q/K/V from hi/lo bf16 planes.
// Scores: 3-pass split bf16 mma; softmax fp32; PV: 3-pass with P split on the fly.
// Smem tiles 64x64 bf16, chunk-swizzled: off(r,c) = (r*8 + (c^(r&7)))*16.
// ----------------------------------------------------------------------------
#define TOFF_Q1H 0
#define TOFF_Q2H 8192
#define TOFF_Q1L 16384
#define TOFF_Q2L 24576
#define TOFF_K1H 32768
#define TOFF_K2H 40960
#define TOFF_K1L 49152
#define TOFF_K2L 57344
#define TOFF_VH  65536
#define TOFF_VL  73728
#define FA_SMEM 81920

__global__ void __launch_bounds__(128) diff_flash_tc(
    const bf16* __restrict__ Qh, const bf16* __restrict__ Ql,
    const bf16* __restrict__ Kh, const bf16* __restrict__ Kl,
    const bf16* __restrict__ Vh, const bf16* __restrict__ Vl,
    bf16* __restrict__ Oh, bf16* __restrict__ Ol,
    const float* __restrict__ lam, int causal) {
    extern __shared__ char smc[];
    const uint32_t smb = (uint32_t)__cvta_generic_to_shared(smc);

    const int tid = threadIdx.x;
    const int lane = tid & 31;
    const int warp = tid >> 5;
    const int g = lane >> 2, tg = lane & 3;
    const int b = blockIdx.y >> 4, h = blockIdx.y & 15;
    const int t0 = blockIdx.x * 64;
    const size_t qrow0 = (size_t)b * 1024 + t0;

    auto ldtile = [&](uint32_t soff, const bf16* src, size_t rowbase, int stride, int colbase) {
        #pragma unroll
        for (int i = 0; i < 4; i++) {
            int id = tid + i * 128;
            int r = id >> 3, c = id & 7;
            cp16(smb + soff + ((r * 8 + (c ^ (r & 7))) << 4),
                 src + (rowbase + r) * (size_t)stride + colbase + c * 8);
        }
    };

    // Q tiles (held for whole kernel)
    ldtile(TOFF_Q1H, Qh, qrow0, 2048, h * 128);
    ldtile(TOFF_Q2H, Qh, qrow0, 2048, h * 128 + 64);
    ldtile(TOFF_Q1L, Ql, qrow0, 2048, h * 128);
    ldtile(TOFF_Q2L, Ql, qrow0, 2048, h * 128 + 64);
    cp_commit();

    float oa[2][8][4];
    float mrow[2][2], lrow[2][2];
    #pragma unroll
    for (int st = 0; st < 2; st++) {
        #pragma unroll
        for (int n = 0; n < 8; n++)
            #pragma unroll
            for (int j = 0; j < 4; j++) oa[st][n][j] = 0.f;
        mrow[st][0] = -1e30f; mrow[st][1] = -1e30f;
        lrow[st][0] = 0.f; lrow[st][1] = 0.f;
    }

    const int nS = causal ? ((int)blockIdx.x + 1) : 16;

    for (int si = 0; si < nS; si++) {
        __syncthreads();
        const size_t krow0 = (size_t)b * 1024 + si * 64;
        ldtile(TOFF_K1H, Kh, krow0, 2048, h * 128);
        ldtile(TOFF_K2H, Kh, krow0, 2048, h * 128 + 64);
        ldtile(TOFF_K1L, Kl, krow0, 2048, h * 128);
        ldtile(TOFF_K2L, Kl, krow0, 2048, h * 128 + 64);
        ldtile(TOFF_VH, Vh, krow0, 1024, h * 64);
        ldtile(TOFF_VL, Vl, krow0, 1024, h * 64);
        cp_commit();
        asm volatile("cp.async.wait_group 0;\n" ::: "memory");
        __syncthreads();

        const bool diag = causal && (si == (int)blockIdx.x);

        #pragma unroll
        for (int st = 0; st < 2; st++) {
            const uint32_t qhb = smb + (st ? TOFF_Q2H : TOFF_Q1H);
            const uint32_t qlb = smb + (st ? TOFF_Q2L : TOFF_Q1L);
            const uint32_t khb = smb + (st ? TOFF_K2H : TOFF_K1H);
            const uint32_t klb = smb + (st ? TOFF_K2L : TOFF_K1L);

            float sacc[8][4];
            #pragma unroll
            for (int n = 0; n < 8; n++)
                #pragma unroll
                for (int j = 0; j < 4; j++) sacc[n][j] = 0.f;

            // scores: S = Q K^T (split 3-pass)
            #pragma unroll
            for (int t = 0; t < 4; t++) {
                uint32_t qf_h[4], qf_l[4];
                {
                    int r = warp * 16 + (lane & 15);
                    int c = 2 * t + (lane >> 4);
                    uint32_t off = (uint32_t)((r * 8 + (c ^ (r & 7))) << 4);
                    ldsm4(qhb + off, qf_h);
                    ldsm4(qlb + off, qf_l);
                }
                #pragma unroll
                for (int nb = 0; nb < 4; nb++) {
                    int r = nb * 16 + (lane & 15);
                    int c = 2 * t + (lane >> 4);
                    uint32_t off = (uint32_t)((r * 8 + (c ^ (r & 7))) << 4);
                    uint32_t kf_h[4], kf_l[4];
                    ldsm4(khb + off, kf_h);
                    ldsm4(klb + off, kf_l);
                    mma_bf16(sacc[2 * nb],     qf_h, kf_h[0], kf_h[2]);
                    mma_bf16(sacc[2 * nb + 1], qf_h, kf_h[1], kf_h[3]);
                    mma_bf16(sacc[2 * nb],     qf_h, kf_l[0], kf_l[2]);
                    mma_bf16(sacc[2 * nb + 1], qf_h, kf_l[1], kf_l[3]);
                    mma_bf16(sacc[2 * nb],     qf_l, kf_h[0], kf_h[2]);
                    mma_bf16(sacc[2 * nb + 1], qf_l, kf_h[1], kf_h[3]);
                }
            }

            // scale + causal mask
            #pragma unroll
            for (int n = 0; n < 8; n++)
                #pragma unroll
                for (int j = 0; j < 4; j++) {
                    float v = sacc[n][j] * 0.125f;
                    if (diag) {
                        int rq = warp * 16 + g + 8 * (j >> 1);
                        int ck = n * 8 + 2 * tg + (j & 1);
                        if (ck > rq) v = -1e9f;
                    }
                    sacc[n][j] = v;
                }

            // online softmax (fp32), rows g / g+8 per thread
            #pragma unroll
            for (int h2 = 0; h2 < 2; h2++) {
                float mx = -1e30f;
                #pragma unroll
                for (int n = 0; n < 8; n++)
                    mx = fmaxf(mx, fmaxf(sacc[n][h2 * 2], sacc[n][h2 * 2 + 1]));
                mx = fmaxf(mx, __shfl_xor_sync(0xffffffffu, mx, 1));
                mx = fmaxf(mx, __shfl_xor_sync(0xffffffffu, mx, 2));
                float mn = fmaxf(mrow[st][h2], mx);
                float corr = __expf(mrow[st][h2] - mn);
                mrow[st][h2] = mn;
                float rs = 0.f;
                #pragma unroll
                for (int n = 0; n < 8; n++) {
                    float p0 = __expf(sacc[n][h2 * 2] - mn);
                    float p1 = __expf(sacc[n][h2 * 2 + 1] - mn);
                    sacc[n][h2 * 2] = p0;
                    sacc[n][h2 * 2 + 1] = p1;
                    rs += p0 + p1;
                }
                rs += __shfl_xor_sync(0xffffffffu, rs, 1);
                rs += __shfl_xor_sync(0xffffffffu, rs, 2);
                lrow[st][h2] = lrow[st][h2] * corr + rs;
                #pragma unroll
                for (int n = 0; n < 8; n++) {
                    oa[st][n][h2 * 2] *= corr;
                    oa[st][n][h2 * 2 + 1] *= corr;
                }
            }

            // PV: O += P V (split 3-pass); P fragments built from sacc directly
            #pragma unroll
            for (int t = 0; t < 4; t++) {
                uint32_t ph[4], pl[4];
                split_pack(sacc[2 * t][0], sacc[2 * t][1], ph[0], pl[0]);
                split_pack(sacc[2 * t][2], sacc[2 * t][3], ph[1], pl[1]);
                split_pack(sacc[2 * t + 1][0], sacc[2 * t + 1][1], ph[2], pl[2]);
                split_pack(sacc[2 * t + 1][2], sacc[2 * t + 1][3], ph[3], pl[3]);
                #pragma unroll
                for (int u = 0; u < 4; u++) {
                    int r = t * 16 + (lane & 15);
                    int c = 2 * u + (lane >> 4);
                    uint32_t off = (uint32_t)((r * 8 + (c ^ (r & 7))) << 4);
                    uint32_t vf_h[4], vf_l[4];
                    ldsm4t(smb + TOFF_VH + off, vf_h);
                    ldsm4t(smb + TOFF_VL + off, vf_l);
                    mma_bf16(oa[st][2 * u],     ph, vf_h[0], vf_h[1]);
                    mma_bf16(oa[st][2 * u + 1], ph, vf_h[2], vf_h[3]);
                    mma_bf16(oa[st][2 * u],     ph, vf_l[0], vf_l[1]);
                    mma_bf16(oa[st][2 * u + 1], ph, vf_l[2], vf_l[3]);
                    mma_bf16(oa[st][2 * u],     pl, vf_h[0], vf_h[1]);
                    mma_bf16(oa[st][2 * u + 1], pl, vf_h[2], vf_h[3]);
                }
            }
        }
    }

    // epilogue: combine streams, per-row rmsnorm over hs, *0.2, write planes
    const float lamv = lam[h];
    #pragma unroll
    for (int h2 = 0; h2 < 2; h2++) {
        float inv1 = 1.f / lrow[0][h2];
        float inv2 = 1.f / lrow[1][h2];
        float vv[8][2];
        float ss = 0.f;
        #pragma unroll
        for (int n = 0; n < 8; n++) {
            #pragma unroll
            for (int j = 0; j < 2; j++) {
                float v = oa[0][n][h2 * 2 + j] * inv1 - lamv * (oa[1][n][h2 * 2 + j] * inv2);
                vv[n][j] = v;
                ss += v * v;
            }
        }
        ss += __shfl_xor_sync(0xffffffffu, ss, 1);
        ss += __shfl_xor_sync(0xffffffffu, ss, 2);
        float rn = rsqrtf(ss * (1.0f / 64.0f) + 1e-6f) * 0.2f;
        size_t orow = (qrow0 + warp * 16 + g + 8 * h2) * 1024 + h * 64;
        #pragma unroll
        for (int n = 0; n < 8; n++) {
            float v0 = vv[n][0] * rn, v1 = vv[n][1] * rn;
            bf16 h0, l0, h1, l1;
            split_bf16(v0, h0, l0);
            split_bf16(v1, h1, l1);
            *(bf162*)(Oh + orow + n * 8 + 2 * tg) = __halves2bfloat162(h0, h1);
            *(bf162*)(Ol + orow + n * 8 + 2 * tg) = __halves2bfloat162(l0, l1);
        }
    }
}

// ----------------------------------------------------------------------------
// y = silu(g1) * g2 -> hi/lo planes
// ----------------------------------------------------------------------------
__global__ void silu_mul_kernel(const float* __restrict__ g1, const float* __restrict__ g2,
                                bf16* __restrict__ yh, bf16* __restrict__ yl, int n4) {
    int i = blockIdx.x * blockDim.x + threadIdx.x;
    int stride = gridDim.x * blockDim.x;
    for (; i < n4; i += stride) {
        float4 a = ((const float4*)g1)[i];
        float4 b = ((const float4*)g2)[i];
        float4 r;
        r.x = a.x / (1.f + __expf(-a.x)) * b.x;
        r.y = a.y / (1.f + __expf(-a.y)) * b.y;
        r.z = a.z / (1.f + __expf(-a.z)) * b.z;
        r.w = a.w / (1.f + __expf(-a.w)) * b.w;
        bf16 h0, l0, h1, l1, h2, l2, h3, l3;
        split_bf16(r.x, h0, l0);
        split_bf16(r.y, h1, l1);
        split_bf16(r.z, h2, l2);
        split_bf16(r.w, h3, l3);
        ((bf162*)yh)[i * 2 + 0] = __halves2bfloat162(h0, h1);
        ((bf162*)yh)[i * 2 + 1] = __halves2bfloat162(h2, h3);
        ((bf162*)yl)[i * 2 + 0] = __halves2bfloat162(l0, l1);
        ((bf162*)yl)[i * 2 + 1] = __halves2bfloat162(l2, l3);
    }
}

// ----------------------------------------------------------------------------
// kernel_launch
// ----------------------------------------------------------------------------
#define SYM(v, s) cudaGetSymbolAddress((void**)&v, s)

extern "C" void kernel_launch(void* const* d_in, const int* in_sizes, int n_in,
                              void* d_out, int out_size) {
    const float* x     = (const float*)d_in[0];
    const float* enc   = (const float*)d_in[1];
    const float* Wq_s  = (const float*)d_in[2];
    const float* Wk_s  = (const float*)d_in[3];
    const float* Wv_s  = (const float*)d_in[4];
    const float* Wo_s  = (const float*)d_in[5];
    const float* lq1_s = (const float*)d_in[6];
    const float* lk1_s = (const float*)d_in[7];
    const float* lq2_s = (const float*)d_in[8];
    const float* lk2_s = (const float*)d_in[9];
    const float* Wq_c  = (const float*)d_in[10];
    const float* Wk_c  = (const float*)d_in[11];
    const float* Wv_c  = (const float*)d_in[12];
    const float* Wo_c  = (const float*)d_in[13];
    const float* lq1_c = (const float*)d_in[14];
    const float* lk1_c = (const float*)d_in[15];
    const float* lq2_c = (const float*)d_in[16];
    const float* lk2_c = (const float*)d_in[17];
    const float* grms  = (const float*)d_in[18];
    const float* W1    = (const float*)d_in[19];
    const float* W2    = (const float*)d_in[20];
    const float* W3    = (const float*)d_in[21];
    float* out = (float*)d_out;

    float *h0f, *h2, *G1, *G2, *lam;
    SYM(h0f, g_h0f); SYM(h2, g_h2); SYM(G1, g_G1); SYM(G2, g_G2); SYM(lam, g_lam);

    bf16 *h0h, *h0l, *Qh, *Ql, *Kh, *Kl, *Vh, *Vl;
    bf16 *Obh, *Obl, *h1h, *h1l, *ench, *encl, *h3h, *h3l, *Gh, *Gl;
    SYM(h0h, g_h0h); SYM(h0l, g_h0l);
    SYM(Qh, g_Qh); SYM(Ql, g_Ql); SYM(Kh, g_Kh); SYM(Kl, g_Kl);
    SYM(Vh, g_Vh); SYM(Vl, g_Vl);
    SYM(Obh, g_Obh); SYM(Obl, g_Obl);
    SYM(h1h, g_h1h); SYM(h1l, g_h1l); SYM(ench, g_ench); SYM(encl, g_encl);
    SYM(h3h, g_h3h); SYM(h3l, g_h3l); SYM(Gh, g_Gh); SYM(Gl, g_Gl);

    bf16 *Wqsh, *Wqsl, *Wksh, *Wksl, *Wvsh, *Wvsl, *Wosh, *Wosl;
    bf16 *Wqch, *Wqcl, *Wkch, *Wkcl, *Wvch, *Wvcl, *Woch, *Wocl;
    bf16 *W1h, *W1l, *W2h, *W2l, *W3h, *W3l;
    SYM(Wqsh, g_Wqsh); SYM(Wqsl, g_Wqsl); SYM(Wksh, g_Wksh); SYM(Wksl, g_Wksl);
    SYM(Wvsh, g_Wvsh); SYM(Wvsl, g_Wvsl); SYM(Wosh, g_Wosh); SYM(Wosl, g_Wosl);
    SYM(Wqch, g_Wqch); SYM(Wqcl, g_Wqcl); SYM(Wkch, g_Wkch); SYM(Wkcl, g_Wkcl);
    SYM(Wvch, g_Wvch); SYM(Wvcl, g_Wvcl); SYM(Woch, g_Woch); SYM(Wocl, g_Wocl);
    SYM(W1h, g_W1h); SYM(W1l, g_W1l); SYM(W2h, g_W2h); SYM(W2l, g_W2l);
    SYM(W3h, g_W3h); SYM(W3l, g_W3l);

    cudaFuncSetAttribute(diff_flash_tc, cudaFuncAttributeMaxDynamicSharedMemorySize, FA_SMEM);
    cudaFuncSetAttribute(bf16_gemm<false, false>, cudaFuncAttributeMaxDynamicSharedMemorySize, GEMM_SMEM);
    cudaFuncSetAttribute(bf16_gemm<false, true>, cudaFuncAttributeMaxDynamicSharedMemorySize, GEMM_SMEM);
    cudaFuncSetAttribute(bf16_gemm<true, false>, cudaFuncAttributeMaxDynamicSharedMemorySize, GEMM_SMEM);
    cudaFuncSetAttribute(bf16_gemm<true, true>, cudaFuncAttributeMaxDynamicSharedMemorySize, GEMM_SMEM);

    lambda_kernel<<<1, 512>>>(lq1_s, lk1_s, lq2_s, lk2_s, lam);
    lambda_kernel<<<1, 512>>>(lq1_c, lk1_c, lq2_c, lk2_c, lam + 16);

    convert_kernel<<<2048, 256>>>(Wq_s, Wqsh, Wqsl, 1024 * 2048 / 4);
    convert_kernel<<<2048, 256>>>(Wk_s, Wksh, Wksl, 1024 * 2048 / 4);
    convert_kernel<<<1024, 256>>>(Wv_s, Wvsh, Wvsl, 1024 * 1024 / 4);
    convert_kernel<<<1024, 256>>>(Wo_s, Wosh, Wosl, 1024 * 1024 / 4);
    convert_kernel<<<2048, 256>>>(Wq_c, Wqch, Wqcl, 1024 * 2048 / 4);
    convert_kernel<<<2048, 256>>>(Wk_c, Wkch, Wkcl, 1024 * 2048 / 4);
    convert_kernel<<<1024, 256>>>(Wv_c, Wvch, Wvcl, 1024 * 1024 / 4);
    convert_kernel<<<1024, 256>>>(Wo_c, Woch, Wocl, 1024 * 1024 / 4);
    convert_kernel<<<4096, 256>>>(W1, W1h, W1l, 1024 * 4096 / 4);
    convert_kernel<<<4096, 256>>>(W2, W2h, W2l, 1024 * 4096 / 4);
    convert_kernel<<<4096, 256>>>(W3, W3h, W3l, 4096 * 1024 / 4);
    convert_kernel<<<4096, 256>>>(enc, ench, encl, 4096 * 1024 / 4);

    rmsnorm_kernel<3><<<4096, 256>>>(x, grms, h0f, h0h, h0l);

    // ---- self attention (causal) ----
    bf16_gemm<false, true><<<dim3(16, 32), 256, GEMM_SMEM>>>(
        h0h, h0l, Wqsh, Wqsl, nullptr, Qh, Ql, nullptr, 4096, 2048, 1024, 1.f);
    bf16_gemm<false, true><<<dim3(16, 32), 256, GEMM_SMEM>>>(
        h0h, h0l, Wksh, Wksl, nullptr, Kh, Kl, nullptr, 4096, 2048, 1024, 1.f);
    bf16_gemm<false, true><<<dim3(8, 32), 256, GEMM_SMEM>>>(
        h0h, h0l, Wvsh, Wvsl, nullptr, Vh, Vl, nullptr, 4096, 1024, 1024, 1.f);
    diff_flash_tc<<<dim3(16, 64), 128, FA_SMEM>>>(Qh, Ql, Kh, Kl, Vh, Vl, Obh, Obl, lam, 1);
    bf16_gemm<true, true><<<dim3(8, 32), 256, GEMM_SMEM>>>(
        Obh, Obl, Wosh, Wosl, nullptr, h1h, h1l, h0f, 4096, 1024, 1024, 1.f);

    // ---- cross attention (non-causal) ----
    bf16_gemm<false, true><<<dim3(16, 32), 256, GEMM_SMEM>>>(
        h1h, h1l, Wqch, Wqcl, nullptr, Qh, Ql, nullptr, 4096, 2048, 1024, 1.f);
    bf16_gemm<false, true><<<dim3(16, 32), 256, GEMM_SMEM>>>(
        ench, encl, Wkch, Wkcl, nullptr, Kh, Kl, nullptr, 4096, 2048, 1024, 1.f);
    bf16_gemm<false, true><<<dim3(8, 32), 256, GEMM_SMEM>>>(
        ench, encl, Wvch, Wvcl, nullptr, Vh, Vl, nullptr, 4096, 1024, 1024, 1.f);
    diff_flash_tc<<<dim3(16, 64), 128, FA_SMEM>>>(Qh, Ql, Kh, Kl, Vh, Vl, Obh, Obl, lam + 16, 0);
    bf16_gemm<false, false><<<dim3(8, 32), 256, GEMM_SMEM>>>(
        Obh, Obl, Woch, Wocl, h2, nullptr, nullptr, nullptr, 4096, 1024, 1024, 2.f);

    // ---- FFN ----
    rmsnorm_kernel<2><<<4096, 256>>>(h2, grms, nullptr, h3h, h3l);
    bf16_gemm<false, false><<<dim3(32, 32), 256, GEMM_SMEM>>>(
        h3h, h3l, W1h, W1l, G1, nullptr, nullptr, nullptr, 4096, 4096, 1024, 1.f);
    bf16_gemm<false, false><<<dim3(32, 32), 256, GEMM_SMEM>>>(
        h3h, h3l, W2h, W2l, G2, nullptr, nullptr, nullptr, 4096, 4096, 1024, 1.f);
    silu_mul_kernel<<<4096, 256>>>(G1, G2, Gh, Gl, 4096 * 4096 / 4);
    bf16_gemm<true, false><<<dim3(8, 32), 256, GEMM_SMEM>>>(
        Gh, Gl, W3h, W3l, out, nullptr, nullptr, h2, 4096, 1024, 4096, 1.f);
}